// round 6
// baseline (speedup 1.0000x reference)
#include <cuda_runtime.h>
#include <math.h>

#define Bb 4
#define Nn 128
#define Pp 512
#define Ee 32
#define Kb1 27          // Phase-B k-blocks (108 = 64 hj + 32 e + 9 geom + 3 pad)
#define FfP 112         // feat row stride (108 used)
#define TJ 128          // j-tile rows
#define NTILE 5         // 640 / 128
#define HS 68           // hid/m row stride
#define NT 512          // threads per CTA

typedef unsigned long long u64;

struct __align__(16) Smem {
    float Wm1t[Kb1 * 256];  // transposed k-blocked: [kblk][c][4k]
    float Wm2t[16 * 256];
    float Wx1t[16 * 256];
    float Wx2[64 * 3];
    float bm1h[64];         // bm1 + hi @ Wm1[0:64]
    float bm2[64];
    float bx1[64];
    float bx2[4];
    float feat[TJ * FfP];   // 128 x 112 ; reused as m (stride HS) after Phase B
    float hid[TJ * HS];     // 128 x 68
    float hi[64];
    float maskj[TJ];
    float rotq[TJ * 4];
    float xred[TJ * 3];
    float msum_part[8 * 64];
    float msum[64];
    float hidf[64];
    float hidt[64];
    float hidq[64];
    float traw[16];
    float dqraw[4];
    float xacc[4];
    float qi[4];
    float xi[4];
    float nn;
};

#define FMA2(D_, A_, B_) \
    asm("fma.rn.f32x2 %0, %1, %2, %3;" : "=l"(D_) : "l"(A_), "l"(B_), "l"(D_))

__device__ __forceinline__ float unpack_sum(u64 v) {
    float lo, hi;
    asm("mov.b64 {%0, %1}, %2;" : "=f"(lo), "=f"(hi) : "l"(v));
    return lo + hi;
}

// 4x4 output tile via packed f32x2 FMA, k-pair accumulation.
// src: 4 rows (stride SS, k contiguous). wt: transposed k-blocked weights,
// already offset to this thread's 4-col group (cb*16).
template<int KB, int SS>
__device__ __forceinline__ void gemm2(const float* __restrict__ src,
                                      const float* __restrict__ wt,
                                      u64 acc[4][4])
{
    #pragma unroll 2
    for (int kb = 0; kb < KB; kb++) {
        ulonglong2 a0 = *(const ulonglong2*)(src + 0 * SS + kb * 4);
        ulonglong2 a1 = *(const ulonglong2*)(src + 1 * SS + kb * 4);
        ulonglong2 a2 = *(const ulonglong2*)(src + 2 * SS + kb * 4);
        ulonglong2 a3 = *(const ulonglong2*)(src + 3 * SS + kb * 4);
        ulonglong2 w0 = *(const ulonglong2*)(wt + kb * 256 + 0);
        ulonglong2 w1 = *(const ulonglong2*)(wt + kb * 256 + 4);
        ulonglong2 w2 = *(const ulonglong2*)(wt + kb * 256 + 8);
        ulonglong2 w3 = *(const ulonglong2*)(wt + kb * 256 + 12);
        FMA2(acc[0][0], a0.x, w0.x); FMA2(acc[0][0], a0.y, w0.y);
        FMA2(acc[0][1], a0.x, w1.x); FMA2(acc[0][1], a0.y, w1.y);
        FMA2(acc[0][2], a0.x, w2.x); FMA2(acc[0][2], a0.y, w2.y);
        FMA2(acc[0][3], a0.x, w3.x); FMA2(acc[0][3], a0.y, w3.y);
        FMA2(acc[1][0], a1.x, w0.x); FMA2(acc[1][0], a1.y, w0.y);
        FMA2(acc[1][1], a1.x, w1.x); FMA2(acc[1][1], a1.y, w1.y);
        FMA2(acc[1][2], a1.x, w2.x); FMA2(acc[1][2], a1.y, w2.y);
        FMA2(acc[1][3], a1.x, w3.x); FMA2(acc[1][3], a1.y, w3.y);
        FMA2(acc[2][0], a2.x, w0.x); FMA2(acc[2][0], a2.y, w0.y);
        FMA2(acc[2][1], a2.x, w1.x); FMA2(acc[2][1], a2.y, w1.y);
        FMA2(acc[2][2], a2.x, w2.x); FMA2(acc[2][2], a2.y, w2.y);
        FMA2(acc[2][3], a2.x, w3.x); FMA2(acc[2][3], a2.y, w3.y);
        FMA2(acc[3][0], a3.x, w0.x); FMA2(acc[3][0], a3.y, w0.y);
        FMA2(acc[3][1], a3.x, w1.x); FMA2(acc[3][1], a3.y, w1.y);
        FMA2(acc[3][2], a3.x, w2.x); FMA2(acc[3][2], a3.y, w2.y);
        FMA2(acc[3][3], a3.x, w3.x); FMA2(acc[3][3], a3.y, w3.y);
    }
}

__global__ void __launch_bounds__(NT, 1)
egnn_kernel(const float* __restrict__ q, const float* __restrict__ x,
            const float* __restrict__ h, const float* __restrict__ e,
            const int* __restrict__ node_mask,
            const float* __restrict__ pq, const float* __restrict__ px,
            const float* __restrict__ pe, const float* __restrict__ ph,
            const int* __restrict__ pmask,
            const float* __restrict__ Wm1, const float* __restrict__ bm1,
            const float* __restrict__ Wm2, const float* __restrict__ bm2,
            const float* __restrict__ Wf1, const float* __restrict__ bf1,
            const float* __restrict__ Wf2, const float* __restrict__ bf2,
            const float* __restrict__ Wx1, const float* __restrict__ bx1,
            const float* __restrict__ Wx2, const float* __restrict__ bx2,
            const float* __restrict__ Wq1, const float* __restrict__ bq1,
            const float* __restrict__ Wq2, const float* __restrict__ bq2,
            const float* __restrict__ Wt1, const float* __restrict__ bt1,
            const float* __restrict__ Wt2, const float* __restrict__ bt2,
            float* __restrict__ out)
{
    extern __shared__ float smem_raw[];
    Smem* s = (Smem*)smem_raw;
    const int i = blockIdx.x;
    const int b = blockIdx.y;
    const int tid = threadIdx.x;

    // ---- stage transposed weights: Wt[kblk][c][kk] = W[kblk*4+kk][c] ----
    // (global reads coalesced: c is the fastest index)
    for (int idx = tid; idx < Kb1 * 256; idx += NT) {
        int c = idx & 63;
        int rest = idx >> 6;          // = kblk*4 + kk
        int kblk = rest >> 2, kk = rest & 3;
        int gk = 64 + kblk * 4 + kk;  // skip first 64 rows (hoisted into bias)
        float v = (gk < 169) ? Wm1[gk * 64 + c] : 0.0f;
        s->Wm1t[kblk * 256 + c * 4 + kk] = v;
    }
    for (int idx = tid; idx < 16 * 256; idx += NT) {
        int c = idx & 63;
        int rest = idx >> 6;
        int kblk = rest >> 2, kk = rest & 3;
        s->Wm2t[kblk * 256 + c * 4 + kk] = Wm2[(kblk * 4 + kk) * 64 + c];
    }
    for (int idx = tid; idx < 16 * 256; idx += NT) {
        int c = idx & 63;
        int rest = idx >> 6;
        int kblk = rest >> 2, kk = rest & 3;
        s->Wx1t[kblk * 256 + c * 4 + kk] = Wx1[(kblk * 4 + kk) * 64 + c];
    }
    {
        const float4* g4 = (const float4*)Wx2;
        float4* s4 = (float4*)s->Wx2;
        for (int idx = tid; idx < 48; idx += NT) s4[idx] = g4[idx];
    }
    if (tid < 64) {
        s->bm2[tid] = bm2[tid];
        s->bx1[tid] = bx1[tid];
        s->hi[tid] = h[(b * Nn + i) * 64 + tid];
    }
    if (tid < 3) s->bx2[tid] = bx2[tid];
    if (tid < 4) s->qi[tid] = q[(b * Nn + i) * 4 + tid];
    if (tid < 3) s->xi[tid] = x[(b * Nn + i) * 3 + tid];
    if (tid < 8 * 64) s->msum_part[tid] = 0.0f;
    if (tid == 0) s->nn = -1.0f;  // n_neigh has a -1 term
    __syncthreads();

    // n_neigh = sum(node_mask[b]) + sum(pocket_mask[b]) - 1
    {
        float cnt = 0.0f;
        for (int jj = tid; jj < Nn; jj += NT) cnt += node_mask[b * Nn + jj] ? 1.0f : 0.0f;
        for (int jj = tid; jj < Pp; jj += NT) cnt += pmask[b * Pp + jj] ? 1.0f : 0.0f;
        #pragma unroll
        for (int off = 16; off; off >>= 1) cnt += __shfl_down_sync(0xffffffff, cnt, off);
        if ((tid & 31) == 0) atomicAdd(&s->nn, cnt);
    }
    // hoisted bias: bm1h = bm1 + hi @ Wm1[0:64]  (hi constant per CTA)
    if (tid < 64) {
        float acc = bm1[tid];
        #pragma unroll 4
        for (int k = 0; k < 64; k++) acc += s->hi[k] * Wm1[k * 64 + tid];
        s->bm1h[tid] = acc;
    }
    __syncthreads();

    const float qiw = s->qi[0], qix = s->qi[1], qiy = s->qi[2], qiz = s->qi[3];
    const float xi0 = s->xi[0], xi1 = s->xi[1], xi2 = s->xi[2];
    const int mi = node_mask[b * Nn + i];

    float xacc0 = 0.0f, xacc1 = 0.0f, xacc2 = 0.0f;  // live in tid<128 only

    const int jb = tid >> 4;      // 0..31 -> block of 4 j rows
    const int cb = tid & 15;      // 0..15 -> block of 4 output cols
    float* const mb = s->feat;    // m overlay (stride HS)

    for (int tile = 0; tile < NTILE; tile++) {
        const int j0 = tile * TJ;

        // ---------- Phase A: build feature tile (k-major: hj | e | geom) ----------
        for (int idx = tid; idx < TJ * 16; idx += NT) {
            int row = idx >> 4, c = idx & 15;
            int j = j0 + row;
            const float4* hrow = (j < Nn) ? (const float4*)&h[(b * Nn + j) * 64]
                                          : (const float4*)&ph[(b * Pp + (j - Nn)) * 64];
            *(float4*)&s->feat[row * FfP + c * 4] = hrow[c];
        }
        for (int idx = tid; idx < TJ * 8; idx += NT) {
            int row = idx >> 3, c = idx & 7;
            int j = j0 + row;
            const float4* erow = (j < Nn)
                ? (const float4*)&e[((size_t)(b * Nn + i) * Nn + j) * Ee]
                : (const float4*)&pe[((size_t)(b * Nn + i) * Pp + (j - Nn)) * Ee];
            *(float4*)&s->feat[row * FfP + 64 + c * 4] = erow[c];
        }
        if (tid < TJ) {
            int j = j0 + tid;
            float qjw, qjx, qjy, qjz, xj0, xj1, xj2;
            int mj;
            if (j < Nn) {
                const float* qp = &q[(b * Nn + j) * 4];
                qjw = qp[0]; qjx = qp[1]; qjy = qp[2]; qjz = qp[3];
                const float* xp = &x[(b * Nn + j) * 3];
                xj0 = xp[0]; xj1 = xp[1]; xj2 = xp[2];
                mj = (node_mask[b * Nn + j] && (j != i)) ? 1 : 0;
            } else {
                int jp = j - Nn;
                const float* qp = &pq[(b * Pp + jp) * 4];
                qjw = qp[0]; qjx = qp[1]; qjy = qp[2]; qjz = qp[3];
                const float* xp = &px[(b * Pp + jp) * 3];
                xj0 = xp[0]; xj1 = xp[1]; xj2 = xp[2];
                mj = pmask[b * Pp + jp] ? 1 : 0;
            }
            s->maskj[tid] = (mi && mj) ? 1.0f : 0.0f;

            float d0 = xi0 - xj0, d1 = xi1 - xj1, dz = xi2 - xj2;
            float dd = d0 * d0 + d1 * d1 + dz * dz;
            float qd = fabsf(qiw * qjw + qix * qjx + qiy * qjy + qiz * qjz);
            float vx = -qjx, vy = -qjy, vz = -qjz;      // conj_j vector part
            float tx = 2.0f * (vy * dz - vz * d1);
            float ty = 2.0f * (vz * d0 - vx * dz);
            float tz = 2.0f * (vx * d1 - vy * d0);
            float lx0 = d0 + qjw * tx + (vy * tz - vz * ty);
            float lx1 = d1 + qjw * ty + (vz * tx - vx * tz);
            float lx2 = dz + qjw * tz + (vx * ty - vy * tx);
            float lq0 = qjw * qiw - vx * qix - vy * qiy - vz * qiz;
            float lq1 = qjw * qix + vx * qiw + vy * qiz - vz * qiy;
            float lq2 = qjw * qiy - vx * qiz + vy * qiw + vz * qix;
            float lq3 = qjw * qiz + vx * qiy - vy * qix + vz * qiw;
            float* fr = &s->feat[tid * FfP + 96];
            fr[0] = lx0; fr[1] = lx1; fr[2] = lx2;
            fr[3] = lq0; fr[4] = lq1; fr[5] = lq2; fr[6] = lq3;
            fr[7] = dd; fr[8] = qd;
            fr[9] = 0.0f; fr[10] = 0.0f; fr[11] = 0.0f;  // zero pad k=105..107
            float qn = fmaxf(sqrtf(qjw * qjw + qjx * qjx + qjy * qjy + qjz * qjz), 1e-12f);
            float inv = 1.0f / qn;
            s->rotq[tid * 4 + 0] = qjw * inv;
            s->rotq[tid * 4 + 1] = qjx * inv;
            s->rotq[tid * 4 + 2] = qjy * inv;
            s->rotq[tid * 4 + 3] = qjz * inv;
        }
        __syncthreads();

        // ---------- Phase B: hid = relu(feat @ Wm1[64:] + bm1h) ----------
        {
            u64 acc[4][4] = {};
            gemm2<Kb1, FfP>(&s->feat[(jb * 4) * FfP], &s->Wm1t[cb * 16], acc);
            float4 bb = *(const float4*)&s->bm1h[cb * 4];
            float* hr = &s->hid[(jb * 4) * HS + cb * 4];
            #pragma unroll
            for (int r = 0; r < 4; r++) {
                float4 o;
                o.x = fmaxf(unpack_sum(acc[r][0]) + bb.x, 0.0f);
                o.y = fmaxf(unpack_sum(acc[r][1]) + bb.y, 0.0f);
                o.z = fmaxf(unpack_sum(acc[r][2]) + bb.z, 0.0f);
                o.w = fmaxf(unpack_sum(acc[r][3]) + bb.w, 0.0f);
                *(float4*)(hr + r * HS) = o;
            }
        }
        __syncthreads();

        // ---------- Phase C: m = (hid @ Wm2 + bm2) * mask  (into feat buffer) ----------
        {
            u64 acc[4][4] = {};
            gemm2<16, HS>(&s->hid[(jb * 4) * HS], &s->Wm2t[cb * 16], acc);
            float4 bb = *(const float4*)&s->bm2[cb * 4];
            float* mr = &mb[(jb * 4) * HS + cb * 4];
            #pragma unroll
            for (int r = 0; r < 4; r++) {
                float mk = s->maskj[jb * 4 + r];
                float4 o;
                o.x = (unpack_sum(acc[r][0]) + bb.x) * mk;
                o.y = (unpack_sum(acc[r][1]) + bb.y) * mk;
                o.z = (unpack_sum(acc[r][2]) + bb.z) * mk;
                o.w = (unpack_sum(acc[r][3]) + bb.w) * mk;
                *(float4*)(mr + r * HS) = o;
            }
        }
        __syncthreads();

        // ---------- Phase M: msum partial (reads m) ----------
        {
            int t = tid & 63, g = tid >> 6;
            float ps = 0.0f;
            #pragma unroll
            for (int r = 0; r < 16; r++) ps += mb[(g * 16 + r) * HS + t];
            s->msum_part[g * 64 + t] += ps;
        }

        // ---------- Phase D: hid = relu(m @ Wx1 + bx1) ----------
        {
            u64 acc[4][4] = {};
            gemm2<16, HS>(&mb[(jb * 4) * HS], &s->Wx1t[cb * 16], acc);
            float4 bb = *(const float4*)&s->bx1[cb * 4];
            float* hr = &s->hid[(jb * 4) * HS + cb * 4];
            #pragma unroll
            for (int r = 0; r < 4; r++) {
                float4 o;
                o.x = fmaxf(unpack_sum(acc[r][0]) + bb.x, 0.0f);
                o.y = fmaxf(unpack_sum(acc[r][1]) + bb.y, 0.0f);
                o.z = fmaxf(unpack_sum(acc[r][2]) + bb.z, 0.0f);
                o.w = fmaxf(unpack_sum(acc[r][3]) + bb.w, 0.0f);
                *(float4*)(hr + r * HS) = o;
            }
        }
        __syncthreads();

        // ---------- Phase E: dx -> rotate -> accumulate ----------
        if (tid < TJ) {
            float a0 = s->bx2[0], a1 = s->bx2[1], a2 = s->bx2[2];
            const float* hr = &s->hid[tid * HS];
            #pragma unroll 4
            for (int u = 0; u < 64; u++) {
                float hv = hr[u];
                a0 += hv * s->Wx2[u * 3 + 0];
                a1 += hv * s->Wx2[u * 3 + 1];
                a2 += hv * s->Wx2[u * 3 + 2];
            }
            float mk = s->maskj[tid];
            a0 *= mk; a1 *= mk; a2 *= mk;
            float w  = s->rotq[tid * 4 + 0];
            float vx = s->rotq[tid * 4 + 1];
            float vy = s->rotq[tid * 4 + 2];
            float vz = s->rotq[tid * 4 + 3];
            float tx = 2.0f * (vy * a2 - vz * a1);
            float ty = 2.0f * (vz * a0 - vx * a2);
            float tz = 2.0f * (vx * a1 - vy * a0);
            xacc0 += a0 + w * tx + (vy * tz - vz * ty);
            xacc1 += a1 + w * ty + (vz * tx - vx * tz);
            xacc2 += a2 + w * tz + (vx * ty - vy * tx);
        }
        __syncthreads();
    }

    // ---- final msum & xacc staging ----
    if (tid < 64) {
        float acc = 0.0f;
        #pragma unroll
        for (int g = 0; g < 8; g++) acc += s->msum_part[g * 64 + tid];
        s->msum[tid] = acc;
    }
    if (tid < TJ) {
        s->xred[tid * 3 + 0] = xacc0;
        s->xred[tid * 3 + 1] = xacc1;
        s->xred[tid * 3 + 2] = xacc2;
    }
    __syncthreads();

    const int grp = tid >> 6, lt = tid & 63;
    // ---- epilogue hidden layers + xacc reduce ----
    if (grp == 0) {
        float acc = bf1[lt];
        #pragma unroll 4
        for (int k = 0; k < 64; k++) acc += s->hi[k] * Wf1[k * 64 + lt];
        #pragma unroll 4
        for (int k = 0; k < 64; k++) acc += s->msum[k] * Wf1[(64 + k) * 64 + lt];
        s->hidf[lt] = fmaxf(acc, 0.0f);
    } else if (grp == 1) {
        float acc = bt1[lt];
        #pragma unroll 4
        for (int k = 0; k < 64; k++) acc += s->msum[k] * Wt1[k * 64 + lt];
        s->hidt[lt] = fmaxf(acc, 0.0f);
    } else if (grp == 2) {
        float acc = bq1[lt];
        #pragma unroll 4
        for (int k = 0; k < 64; k++) acc += s->msum[k] * Wq1[k * 64 + lt];
        s->hidq[lt] = fmaxf(acc, 0.0f);
    } else if (grp == 3 && lt < 3) {
        float sum = 0.0f;
        #pragma unroll 4
        for (int j = 0; j < TJ; j++) sum += s->xred[j * 3 + lt];
        s->xacc[lt] = sum;
    }
    __syncthreads();

    float* out_q = out;
    float* out_x = out + Bb * Nn * 4;
    float* out_t = out + Bb * Nn * 7;
    float* out_o = out + Bb * Nn * 21;
    const int node = b * Nn + i;

    if (grp == 0) {
        float acc = bf2[lt];
        #pragma unroll 4
        for (int u = 0; u < 64; u++) acc += s->hidf[u] * Wf2[u * 64 + lt];
        out_o[node * 64 + lt] = acc;
    } else if (grp == 1 && lt < 14) {
        float acc = bt2[lt];
        #pragma unroll 4
        for (int u = 0; u < 64; u++) acc += s->hidt[u] * Wt2[u * 14 + lt];
        s->traw[lt] = acc;
    } else if (grp == 2 && lt < 4) {
        float acc = bq2[lt];
        #pragma unroll 4
        for (int u = 0; u < 64; u++) acc += s->hidq[u] * Wq2[u * 4 + lt];
        s->dqraw[lt] = acc;
    }
    __syncthreads();

    if (tid == 0) {
        float d0 = s->dqraw[0], d1 = s->dqraw[1], d2 = s->dqraw[2], d3 = s->dqraw[3];
        if (!mi) { d0 = 1.0f; d1 = 0.0f; d2 = 0.0f; d3 = 0.0f; }
        float nrm = fmaxf(sqrtf(d0 * d0 + d1 * d1 + d2 * d2 + d3 * d3), 1e-12f);
        float inv = 1.0f / nrm;
        d0 *= inv; d1 *= inv; d2 *= inv; d3 *= inv;
        float u0 = qiw * d0 - qix * d1 - qiy * d2 - qiz * d3;
        float u1 = qiw * d1 + qix * d0 + qiy * d3 - qiz * d2;
        float u2 = qiw * d2 - qix * d3 + qiy * d0 + qiz * d1;
        float u3 = qiw * d3 + qix * d2 - qiy * d1 + qiz * d0;
        if (!mi) { u0 = 1.0f; u1 = 0.0f; u2 = 0.0f; u3 = 0.0f; }
        nrm = fmaxf(sqrtf(u0 * u0 + u1 * u1 + u2 * u2 + u3 * u3), 1e-12f);
        inv = 1.0f / nrm;
        out_q[node * 4 + 0] = u0 * inv;
        out_q[node * 4 + 1] = u1 * inv;
        out_q[node * 4 + 2] = u2 * inv;
        out_q[node * 4 + 3] = u3 * inv;
    }
    if (tid >= 4 && tid < 7) {
        int c = tid - 4;
        out_x[node * 3 + c] = s->xi[c] + s->xacc[c] / s->nn;
    }
    if (tid >= 32 && tid < 39) {
        int p = tid - 32;
        float a = s->traw[p * 2 + 0];
        float c = s->traw[p * 2 + 1];
        float nrm = fmaxf(sqrtf(a * a + c * c), 1e-12f);
        out_t[node * 14 + p * 2 + 0] = a / nrm;
        out_t[node * 14 + p * 2 + 1] = c / nrm;
    }
}

extern "C" void kernel_launch(void* const* d_in, const int* in_sizes, int n_in,
                              void* d_out, int out_size)
{
    const float* q  = (const float*)d_in[0];
    const float* x  = (const float*)d_in[1];
    // d_in[2] = torsions (values unused)
    const float* h  = (const float*)d_in[3];
    const float* e  = (const float*)d_in[4];
    const int* node_mask = (const int*)d_in[5];
    const float* pq = (const float*)d_in[6];
    const float* px = (const float*)d_in[7];
    const float* pe = (const float*)d_in[8];
    const float* ph = (const float*)d_in[9];
    const int* pmask = (const int*)d_in[10];
    const float* Wm1 = (const float*)d_in[11];
    const float* bm1 = (const float*)d_in[12];
    const float* Wm2 = (const float*)d_in[13];
    const float* bm2 = (const float*)d_in[14];
    const float* Wf1 = (const float*)d_in[15];
    const float* bf1 = (const float*)d_in[16];
    const float* Wf2 = (const float*)d_in[17];
    const float* bf2 = (const float*)d_in[18];
    const float* Wx1 = (const float*)d_in[19];
    const float* bx1 = (const float*)d_in[20];
    const float* Wx2 = (const float*)d_in[21];
    const float* bx2 = (const float*)d_in[22];
    const float* Wq1 = (const float*)d_in[23];
    const float* bq1 = (const float*)d_in[24];
    const float* Wq2 = (const float*)d_in[25];
    const float* bq2 = (const float*)d_in[26];
    const float* Wt1 = (const float*)d_in[27];
    const float* bt1 = (const float*)d_in[28];
    const float* Wt2 = (const float*)d_in[29];
    const float* bt2 = (const float*)d_in[30];

    const size_t smem = sizeof(Smem);
    cudaFuncSetAttribute(egnn_kernel, cudaFuncAttributeMaxDynamicSharedMemorySize,
                         (int)smem);

    dim3 grid(Nn, Bb);
    egnn_kernel<<<grid, NT, smem>>>(
        q, x, h, e, node_mask, pq, px, pe, ph, pmask,
        Wm1, bm1, Wm2, bm2, Wf1, bf1, Wf2, bf2,
        Wx1, bx1, Wx2, bx2, Wq1, bq1, Wq2, bq2, Wt1, bt1, Wt2, bt2,
        (float*)d_out);
}

// round 7
// speedup vs baseline: 2.0887x; 2.0887x over previous
#include <cuda_runtime.h>
#include <math.h>

#define Bb 4
#define Nn 128
#define Pp 512
#define Ee 32
#define FfP 112         // feat row stride: 64 hj + 32 e + 9 geom + 7 pad
#define TJ 128          // j-tile rows
#define NTILE 5         // 640 / 128
#define HS 68           // hid/m row stride (floats, mult of 4)
#define NT 512          // threads per CTA

struct __align__(16) Smem {
    float Wm1[FfP * 64];   // rows 0..104 = Wm1[64..168], rows 105..111 zero
    float Wm2[64 * 64];
    float Wx1[64 * 64];
    float Wx2[64 * 3];
    float bm1h[64];        // bm1 + hi @ Wm1[0:64]
    float bm2[64];
    float bx1[64];
    float bx2[4];
    float feat[TJ * FfP];  // 128 x 112 ; reused as m (stride HS) after Phase B
    float hid[TJ * HS];    // 128 x 68
    float hi[64];
    float maskj[TJ];
    float rotq[TJ * 4];
    float xred[TJ * 3];
    float msum_part[8 * 64];
    float msum[64];
    float hidf[64];
    float hidt[64];
    float hidq[64];
    float traw[16];
    float dqraw[4];
    float xacc[4];
    float qi[4];
    float xi[4];
    float nn;
};

#define RANK1(CMP_, WV_) \
    acc[0][0] += a0.CMP_ * WV_.x; acc[0][1] += a0.CMP_ * WV_.y; acc[0][2] += a0.CMP_ * WV_.z; acc[0][3] += a0.CMP_ * WV_.w; \
    acc[1][0] += a1.CMP_ * WV_.x; acc[1][1] += a1.CMP_ * WV_.y; acc[1][2] += a1.CMP_ * WV_.z; acc[1][3] += a1.CMP_ * WV_.w; \
    acc[2][0] += a2.CMP_ * WV_.x; acc[2][1] += a2.CMP_ * WV_.y; acc[2][2] += a2.CMP_ * WV_.z; acc[2][3] += a2.CMP_ * WV_.w; \
    acc[3][0] += a3.CMP_ * WV_.x; acc[3][1] += a3.CMP_ * WV_.y; acc[3][2] += a3.CMP_ * WV_.z; acc[3][3] += a3.CMP_ * WV_.w;

// 4x4 output tile, fully vectorized k: src = 4 rows at stride SSTRIDE,
// wcol = weight column block (4 cols), weight row stride 64 floats.
template<int KVCOUNT, int SSTRIDE>
__device__ __forceinline__ void gemm16(const float* __restrict__ src,
                                       const float* __restrict__ wcol,
                                       float acc[4][4])
{
    #pragma unroll 2
    for (int kv = 0; kv < KVCOUNT; kv++) {
        float4 a0 = *(const float4*)(src + 0 * SSTRIDE + kv * 4);
        float4 a1 = *(const float4*)(src + 1 * SSTRIDE + kv * 4);
        float4 a2 = *(const float4*)(src + 2 * SSTRIDE + kv * 4);
        float4 a3 = *(const float4*)(src + 3 * SSTRIDE + kv * 4);
        float4 w0 = *(const float4*)(wcol + (kv * 4 + 0) * 64);
        float4 w1 = *(const float4*)(wcol + (kv * 4 + 1) * 64);
        float4 w2 = *(const float4*)(wcol + (kv * 4 + 2) * 64);
        float4 w3 = *(const float4*)(wcol + (kv * 4 + 3) * 64);
        RANK1(x, w0)
        RANK1(y, w1)
        RANK1(z, w2)
        RANK1(w, w3)
    }
}

__global__ void __launch_bounds__(NT, 1)
egnn_kernel(const float* __restrict__ q, const float* __restrict__ x,
            const float* __restrict__ h, const float* __restrict__ e,
            const int* __restrict__ node_mask,
            const float* __restrict__ pq, const float* __restrict__ px,
            const float* __restrict__ pe, const float* __restrict__ ph,
            const int* __restrict__ pmask,
            const float* __restrict__ Wm1, const float* __restrict__ bm1,
            const float* __restrict__ Wm2, const float* __restrict__ bm2,
            const float* __restrict__ Wf1, const float* __restrict__ bf1,
            const float* __restrict__ Wf2, const float* __restrict__ bf2,
            const float* __restrict__ Wx1, const float* __restrict__ bx1,
            const float* __restrict__ Wx2, const float* __restrict__ bx2,
            const float* __restrict__ Wq1, const float* __restrict__ bq1,
            const float* __restrict__ Wq2, const float* __restrict__ bq2,
            const float* __restrict__ Wt1, const float* __restrict__ bt1,
            const float* __restrict__ Wt2, const float* __restrict__ bt2,
            float* __restrict__ out)
{
    extern __shared__ float smem_raw[];
    Smem* s = (Smem*)smem_raw;
    const int i = blockIdx.x;
    const int b = blockIdx.y;
    const int tid = threadIdx.x;

    // ---- stage weights (vectorized) & node-i data ----
    {
        // Wm1 rows 64..168 -> smem rows 0..104 ; rows 105..111 zero
        const float4* g4 = (const float4*)(Wm1 + 64 * 64);
        float4* s4 = (float4*)s->Wm1;
        for (int idx = tid; idx < 105 * 16; idx += NT) s4[idx] = g4[idx];
        for (int idx = tid; idx < 7 * 16; idx += NT)
            s4[105 * 16 + idx] = make_float4(0.f, 0.f, 0.f, 0.f);
        g4 = (const float4*)Wm2; s4 = (float4*)s->Wm2;
        for (int idx = tid; idx < 1024; idx += NT) s4[idx] = g4[idx];
        g4 = (const float4*)Wx1; s4 = (float4*)s->Wx1;
        for (int idx = tid; idx < 1024; idx += NT) s4[idx] = g4[idx];
        g4 = (const float4*)Wx2; s4 = (float4*)s->Wx2;
        for (int idx = tid; idx < 48; idx += NT) s4[idx] = g4[idx];
    }
    if (tid < 64) {
        s->bm2[tid] = bm2[tid];
        s->bx1[tid] = bx1[tid];
        s->hi[tid] = h[(b * Nn + i) * 64 + tid];
    }
    if (tid < 3) s->bx2[tid] = bx2[tid];
    if (tid < 4) s->qi[tid] = q[(b * Nn + i) * 4 + tid];
    if (tid < 3) s->xi[tid] = x[(b * Nn + i) * 3 + tid];
    if (tid < 8 * 64) s->msum_part[tid] = 0.0f;
    if (tid == 0) s->nn = -1.0f;  // n_neigh has a -1 term
    __syncthreads();

    // n_neigh = sum(node_mask[b]) + sum(pocket_mask[b]) - 1
    {
        float cnt = 0.0f;
        for (int jj = tid; jj < Nn; jj += NT) cnt += node_mask[b * Nn + jj] ? 1.0f : 0.0f;
        for (int jj = tid; jj < Pp; jj += NT) cnt += pmask[b * Pp + jj] ? 1.0f : 0.0f;
        #pragma unroll
        for (int off = 16; off; off >>= 1) cnt += __shfl_down_sync(0xffffffff, cnt, off);
        if ((tid & 31) == 0) atomicAdd(&s->nn, cnt);
    }
    // hoisted bias: bm1h = bm1 + hi @ Wm1[0:64]  (hi is identical for every j-row)
    if (tid < 64) {
        float acc = bm1[tid];
        #pragma unroll 4
        for (int k = 0; k < 64; k++) acc += s->hi[k] * Wm1[k * 64 + tid];
        s->bm1h[tid] = acc;
    }
    __syncthreads();

    const float qiw = s->qi[0], qix = s->qi[1], qiy = s->qi[2], qiz = s->qi[3];
    const float xi0 = s->xi[0], xi1 = s->xi[1], xi2 = s->xi[2];
    const int mi = node_mask[b * Nn + i];

    float xacc0 = 0.0f, xacc1 = 0.0f, xacc2 = 0.0f;  // live in tid<128 only

    const int jb = tid >> 4;      // 0..31 -> block of 4 j rows
    const int cb = tid & 15;      // 0..15 -> block of 4 output cols
    float* const mb = s->feat;    // m overlay (stride HS)

    for (int tile = 0; tile < NTILE; tile++) {
        const int j0 = tile * TJ;

        // ---------- Phase A: build feature tile (hj | e | geom | pad) ----------
        for (int idx = tid; idx < TJ * 16; idx += NT) {
            int row = idx >> 4, c = idx & 15;
            int j = j0 + row;
            const float4* hrow = (j < Nn) ? (const float4*)&h[(b * Nn + j) * 64]
                                          : (const float4*)&ph[(b * Pp + (j - Nn)) * 64];
            *(float4*)&s->feat[row * FfP + c * 4] = hrow[c];
        }
        for (int idx = tid; idx < TJ * 8; idx += NT) {
            int row = idx >> 3, c = idx & 7;
            int j = j0 + row;
            const float4* erow = (j < Nn)
                ? (const float4*)&e[((size_t)(b * Nn + i) * Nn + j) * Ee]
                : (const float4*)&pe[((size_t)(b * Nn + i) * Pp + (j - Nn)) * Ee];
            *(float4*)&s->feat[row * FfP + 64 + c * 4] = erow[c];
        }
        if (tid < TJ) {
            int j = j0 + tid;
            float qjw, qjx, qjy, qjz, xj0, xj1, xj2;
            int mj;
            if (j < Nn) {
                const float* qp = &q[(b * Nn + j) * 4];
                qjw = qp[0]; qjx = qp[1]; qjy = qp[2]; qjz = qp[3];
                const float* xp = &x[(b * Nn + j) * 3];
                xj0 = xp[0]; xj1 = xp[1]; xj2 = xp[2];
                mj = (node_mask[b * Nn + j] && (j != i)) ? 1 : 0;
            } else {
                int jp = j - Nn;
                const float* qp = &pq[(b * Pp + jp) * 4];
                qjw = qp[0]; qjx = qp[1]; qjy = qp[2]; qjz = qp[3];
                const float* xp = &px[(b * Pp + jp) * 3];
                xj0 = xp[0]; xj1 = xp[1]; xj2 = xp[2];
                mj = pmask[b * Pp + jp] ? 1 : 0;
            }
            s->maskj[tid] = (mi && mj) ? 1.0f : 0.0f;

            float d0 = xi0 - xj0, d1 = xi1 - xj1, dz = xi2 - xj2;
            float dd = d0 * d0 + d1 * d1 + dz * dz;
            float qd = fabsf(qiw * qjw + qix * qjx + qiy * qjy + qiz * qjz);
            float vx = -qjx, vy = -qjy, vz = -qjz;      // conj_j vector part
            float tx = 2.0f * (vy * dz - vz * d1);
            float ty = 2.0f * (vz * d0 - vx * dz);
            float tz = 2.0f * (vx * d1 - vy * d0);
            float lx0 = d0 + qjw * tx + (vy * tz - vz * ty);
            float lx1 = d1 + qjw * ty + (vz * tx - vx * tz);
            float lx2 = dz + qjw * tz + (vx * ty - vy * tx);
            float lq0 = qjw * qiw - vx * qix - vy * qiy - vz * qiz;
            float lq1 = qjw * qix + vx * qiw + vy * qiz - vz * qiy;
            float lq2 = qjw * qiy - vx * qiz + vy * qiw + vz * qix;
            float lq3 = qjw * qiz + vx * qiy - vy * qix + vz * qiw;
            float* fr = &s->feat[tid * FfP + 96];
            fr[0] = lx0; fr[1] = lx1; fr[2] = lx2;
            fr[3] = lq0; fr[4] = lq1; fr[5] = lq2; fr[6] = lq3;
            fr[7] = dd; fr[8] = qd;
            fr[9] = 0.0f; fr[10] = 0.0f; fr[11] = 0.0f;   // pad 105..107
            fr[12] = 0.0f; fr[13] = 0.0f; fr[14] = 0.0f; fr[15] = 0.0f; // 108..111
            float qn = fmaxf(sqrtf(qjw * qjw + qjx * qjx + qjy * qjy + qjz * qjz), 1e-12f);
            float inv = 1.0f / qn;
            s->rotq[tid * 4 + 0] = qjw * inv;
            s->rotq[tid * 4 + 1] = qjx * inv;
            s->rotq[tid * 4 + 2] = qjy * inv;
            s->rotq[tid * 4 + 3] = qjz * inv;
        }
        __syncthreads();

        // ---------- Phase B: hid = relu(feat @ Wm1[64:] + bm1h) ----------
        {
            float acc[4][4] = {};
            gemm16<FfP / 4, FfP>(&s->feat[(jb * 4) * FfP], &s->Wm1[cb * 4], acc);
            float4 bb = *(const float4*)&s->bm1h[cb * 4];
            float* hr = &s->hid[(jb * 4) * HS + cb * 4];
            #pragma unroll
            for (int r = 0; r < 4; r++) {
                float4 o;
                o.x = fmaxf(acc[r][0] + bb.x, 0.0f);
                o.y = fmaxf(acc[r][1] + bb.y, 0.0f);
                o.z = fmaxf(acc[r][2] + bb.z, 0.0f);
                o.w = fmaxf(acc[r][3] + bb.w, 0.0f);
                *(float4*)(hr + r * HS) = o;
            }
        }
        __syncthreads();

        // ---------- Phase C: m = (hid @ Wm2 + bm2) * mask  (into feat buffer) ----------
        {
            float acc[4][4] = {};
            gemm16<16, HS>(&s->hid[(jb * 4) * HS], &s->Wm2[cb * 4], acc);
            float4 bb = *(const float4*)&s->bm2[cb * 4];
            float* mr = &mb[(jb * 4) * HS + cb * 4];
            #pragma unroll
            for (int r = 0; r < 4; r++) {
                float mk = s->maskj[jb * 4 + r];
                float4 o;
                o.x = (acc[r][0] + bb.x) * mk;
                o.y = (acc[r][1] + bb.y) * mk;
                o.z = (acc[r][2] + bb.z) * mk;
                o.w = (acc[r][3] + bb.w) * mk;
                *(float4*)(mr + r * HS) = o;
            }
        }
        __syncthreads();

        // ---------- Phase M: msum partial (reads m) ----------
        {
            int t = tid & 63, g = tid >> 6;
            float ps = 0.0f;
            #pragma unroll
            for (int r = 0; r < 16; r++) ps += mb[(g * 16 + r) * HS + t];
            s->msum_part[g * 64 + t] += ps;
        }

        // ---------- Phase D: hid = relu(m @ Wx1 + bx1) ----------
        {
            float acc[4][4] = {};
            gemm16<16, HS>(&mb[(jb * 4) * HS], &s->Wx1[cb * 4], acc);
            float4 bb = *(const float4*)&s->bx1[cb * 4];
            float* hr = &s->hid[(jb * 4) * HS + cb * 4];
            #pragma unroll
            for (int r = 0; r < 4; r++) {
                float4 o;
                o.x = fmaxf(acc[r][0] + bb.x, 0.0f);
                o.y = fmaxf(acc[r][1] + bb.y, 0.0f);
                o.z = fmaxf(acc[r][2] + bb.z, 0.0f);
                o.w = fmaxf(acc[r][3] + bb.w, 0.0f);
                *(float4*)(hr + r * HS) = o;
            }
        }
        __syncthreads();

        // ---------- Phase E: dx -> rotate -> accumulate ----------
        if (tid < TJ) {
            float a0 = s->bx2[0], a1 = s->bx2[1], a2 = s->bx2[2];
            const float* hr = &s->hid[tid * HS];
            #pragma unroll 4
            for (int u = 0; u < 64; u++) {
                float hv = hr[u];
                a0 += hv * s->Wx2[u * 3 + 0];
                a1 += hv * s->Wx2[u * 3 + 1];
                a2 += hv * s->Wx2[u * 3 + 2];
            }
            float mk = s->maskj[tid];
            a0 *= mk; a1 *= mk; a2 *= mk;
            float w  = s->rotq[tid * 4 + 0];
            float vx = s->rotq[tid * 4 + 1];
            float vy = s->rotq[tid * 4 + 2];
            float vz = s->rotq[tid * 4 + 3];
            float tx = 2.0f * (vy * a2 - vz * a1);
            float ty = 2.0f * (vz * a0 - vx * a2);
            float tz = 2.0f * (vx * a1 - vy * a0);
            xacc0 += a0 + w * tx + (vy * tz - vz * ty);
            xacc1 += a1 + w * ty + (vz * tx - vx * tz);
            xacc2 += a2 + w * tz + (vx * ty - vy * tx);
        }
        __syncthreads();
    }

    // ---- final msum & xacc staging ----
    if (tid < 64) {
        float acc = 0.0f;
        #pragma unroll
        for (int g = 0; g < 8; g++) acc += s->msum_part[g * 64 + tid];
        s->msum[tid] = acc;
    }
    if (tid < TJ) {
        s->xred[tid * 3 + 0] = xacc0;
        s->xred[tid * 3 + 1] = xacc1;
        s->xred[tid * 3 + 2] = xacc2;
    }
    __syncthreads();

    const int grp = tid >> 6, lt = tid & 63;
    // ---- epilogue hidden layers + xacc reduce ----
    if (grp == 0) {
        float acc = bf1[lt];
        #pragma unroll 4
        for (int k = 0; k < 64; k++) acc += s->hi[k] * Wf1[k * 64 + lt];
        #pragma unroll 4
        for (int k = 0; k < 64; k++) acc += s->msum[k] * Wf1[(64 + k) * 64 + lt];
        s->hidf[lt] = fmaxf(acc, 0.0f);
    } else if (grp == 1) {
        float acc = bt1[lt];
        #pragma unroll 4
        for (int k = 0; k < 64; k++) acc += s->msum[k] * Wt1[k * 64 + lt];
        s->hidt[lt] = fmaxf(acc, 0.0f);
    } else if (grp == 2) {
        float acc = bq1[lt];
        #pragma unroll 4
        for (int k = 0; k < 64; k++) acc += s->msum[k] * Wq1[k * 64 + lt];
        s->hidq[lt] = fmaxf(acc, 0.0f);
    } else if (grp == 3 && lt < 3) {
        float sum = 0.0f;
        #pragma unroll 4
        for (int j = 0; j < TJ; j++) sum += s->xred[j * 3 + lt];
        s->xacc[lt] = sum;
    }
    __syncthreads();

    float* out_q = out;
    float* out_x = out + Bb * Nn * 4;
    float* out_t = out + Bb * Nn * 7;
    float* out_o = out + Bb * Nn * 21;
    const int node = b * Nn + i;

    if (grp == 0) {
        float acc = bf2[lt];
        #pragma unroll 4
        for (int u = 0; u < 64; u++) acc += s->hidf[u] * Wf2[u * 64 + lt];
        out_o[node * 64 + lt] = acc;
    } else if (grp == 1 && lt < 14) {
        float acc = bt2[lt];
        #pragma unroll 4
        for (int u = 0; u < 64; u++) acc += s->hidt[u] * Wt2[u * 14 + lt];
        s->traw[lt] = acc;
    } else if (grp == 2 && lt < 4) {
        float acc = bq2[lt];
        #pragma unroll 4
        for (int u = 0; u < 64; u++) acc += s->hidq[u] * Wq2[u * 4 + lt];
        s->dqraw[lt] = acc;
    }
    __syncthreads();

    if (tid == 0) {
        float d0 = s->dqraw[0], d1 = s->dqraw[1], d2 = s->dqraw[2], d3 = s->dqraw[3];
        if (!mi) { d0 = 1.0f; d1 = 0.0f; d2 = 0.0f; d3 = 0.0f; }
        float nrm = fmaxf(sqrtf(d0 * d0 + d1 * d1 + d2 * d2 + d3 * d3), 1e-12f);
        float inv = 1.0f / nrm;
        d0 *= inv; d1 *= inv; d2 *= inv; d3 *= inv;
        float u0 = qiw * d0 - qix * d1 - qiy * d2 - qiz * d3;
        float u1 = qiw * d1 + qix * d0 + qiy * d3 - qiz * d2;
        float u2 = qiw * d2 - qix * d3 + qiy * d0 + qiz * d1;
        float u3 = qiw * d3 + qix * d2 - qiy * d1 + qiz * d0;
        if (!mi) { u0 = 1.0f; u1 = 0.0f; u2 = 0.0f; u3 = 0.0f; }
        nrm = fmaxf(sqrtf(u0 * u0 + u1 * u1 + u2 * u2 + u3 * u3), 1e-12f);
        inv = 1.0f / nrm;
        out_q[node * 4 + 0] = u0 * inv;
        out_q[node * 4 + 1] = u1 * inv;
        out_q[node * 4 + 2] = u2 * inv;
        out_q[node * 4 + 3] = u3 * inv;
    }
    if (tid >= 4 && tid < 7) {
        int c = tid - 4;
        out_x[node * 3 + c] = s->xi[c] + s->xacc[c] / s->nn;
    }
    if (tid >= 32 && tid < 39) {
        int p = tid - 32;
        float a = s->traw[p * 2 + 0];
        float c = s->traw[p * 2 + 1];
        float nrm = fmaxf(sqrtf(a * a + c * c), 1e-12f);
        out_t[node * 14 + p * 2 + 0] = a / nrm;
        out_t[node * 14 + p * 2 + 1] = c / nrm;
    }
}

extern "C" void kernel_launch(void* const* d_in, const int* in_sizes, int n_in,
                              void* d_out, int out_size)
{
    const float* q  = (const float*)d_in[0];
    const float* x  = (const float*)d_in[1];
    // d_in[2] = torsions (values unused)
    const float* h  = (const float*)d_in[3];
    const float* e  = (const float*)d_in[4];
    const int* node_mask = (const int*)d_in[5];
    const float* pq = (const float*)d_in[6];
    const float* px = (const float*)d_in[7];
    const float* pe = (const float*)d_in[8];
    const float* ph = (const float*)d_in[9];
    const int* pmask = (const int*)d_in[10];
    const float* Wm1 = (const float*)d_in[11];
    const float* bm1 = (const float*)d_in[12];
    const float* Wm2 = (const float*)d_in[13];
    const float* bm2 = (const float*)d_in[14];
    const float* Wf1 = (const float*)d_in[15];
    const float* bf1 = (const float*)d_in[16];
    const float* Wf2 = (const float*)d_in[17];
    const float* bf2 = (const float*)d_in[18];
    const float* Wx1 = (const float*)d_in[19];
    const float* bx1 = (const float*)d_in[20];
    const float* Wx2 = (const float*)d_in[21];
    const float* bx2 = (const float*)d_in[22];
    const float* Wq1 = (const float*)d_in[23];
    const float* bq1 = (const float*)d_in[24];
    const float* Wq2 = (const float*)d_in[25];
    const float* bq2 = (const float*)d_in[26];
    const float* Wt1 = (const float*)d_in[27];
    const float* bt1 = (const float*)d_in[28];
    const float* Wt2 = (const float*)d_in[29];
    const float* bt2 = (const float*)d_in[30];

    const size_t smem = sizeof(Smem);
    cudaFuncSetAttribute(egnn_kernel, cudaFuncAttributeMaxDynamicSharedMemorySize,
                         (int)smem);

    dim3 grid(Nn, Bb);
    egnn_kernel<<<grid, NT, smem>>>(
        q, x, h, e, node_mask, pq, px, pe, ph, pmask,
        Wm1, bm1, Wm2, bm2, Wf1, bf1, Wf2, bf2,
        Wx1, bx1, Wx2, bx2, Wq1, bq1, Wq2, bq2, Wt1, bt1, Wt2, bt2,
        (float*)d_out);
}

// round 8
// speedup vs baseline: 2.1345x; 1.0219x over previous
#include <cuda_runtime.h>
#include <math.h>

#define Bb 4
#define Nn 128
#define Pp 512
#define Ee 32
#define FfP 112         // feat row stride: 64 hj + 32 e + 9 geom + 7 pad
#define TJ 128          // j-tile rows
#define NTILE 5         // 640 / 128
#define HS 68           // hid/m row stride (floats, mult of 4)
#define NT 512          // threads per CTA

struct __align__(16) Smem {
    float Wm1[FfP * 64];   // rows 0..104 = Wm1[64..168], rows 105..111 zero
    float Wm2[64 * 64];
    float Wx1[64 * 64];
    float Wx2[64 * 3];
    float bm1h[64];        // bm1 + hi @ Wm1[0:64]
    float bm2[64];
    float bx1[64];
    float bx2[4];
    float feat[TJ * FfP];  // 128 x 112 ; reused as m (stride HS) after Phase B
    float hid[TJ * HS];    // 128 x 68
    float hi[64];
    float maskj[TJ];
    float rotq[TJ * 4];
    float msum_part[32 * 64];  // per-jb-group msum partials
    float xpart[TJ * 3];       // per-row xacc partials
    float msum[64];
    float hidf[64];
    float hidt[64];
    float hidq[64];
    float traw[16];
    float dqraw[4];
    float xacc[4];
    float qi[4];
    float xi[4];
    float nn;
};

#define RANK1(CMP_, WV_) \
    acc[0][0] += a0.CMP_ * WV_.x; acc[0][1] += a0.CMP_ * WV_.y; acc[0][2] += a0.CMP_ * WV_.z; acc[0][3] += a0.CMP_ * WV_.w; \
    acc[1][0] += a1.CMP_ * WV_.x; acc[1][1] += a1.CMP_ * WV_.y; acc[1][2] += a1.CMP_ * WV_.z; acc[1][3] += a1.CMP_ * WV_.w; \
    acc[2][0] += a2.CMP_ * WV_.x; acc[2][1] += a2.CMP_ * WV_.y; acc[2][2] += a2.CMP_ * WV_.z; acc[2][3] += a2.CMP_ * WV_.w; \
    acc[3][0] += a3.CMP_ * WV_.x; acc[3][1] += a3.CMP_ * WV_.y; acc[3][2] += a3.CMP_ * WV_.z; acc[3][3] += a3.CMP_ * WV_.w;

template<int KVCOUNT, int SSTRIDE>
__device__ __forceinline__ void gemm16(const float* __restrict__ src,
                                       const float* __restrict__ wcol,
                                       float acc[4][4])
{
    #pragma unroll 2
    for (int kv = 0; kv < KVCOUNT; kv++) {
        float4 a0 = *(const float4*)(src + 0 * SSTRIDE + kv * 4);
        float4 a1 = *(const float4*)(src + 1 * SSTRIDE + kv * 4);
        float4 a2 = *(const float4*)(src + 2 * SSTRIDE + kv * 4);
        float4 a3 = *(const float4*)(src + 3 * SSTRIDE + kv * 4);
        float4 w0 = *(const float4*)(wcol + (kv * 4 + 0) * 64);
        float4 w1 = *(const float4*)(wcol + (kv * 4 + 1) * 64);
        float4 w2 = *(const float4*)(wcol + (kv * 4 + 2) * 64);
        float4 w3 = *(const float4*)(wcol + (kv * 4 + 3) * 64);
        RANK1(x, w0)
        RANK1(y, w1)
        RANK1(z, w2)
        RANK1(w, w3)
    }
}

__global__ void __launch_bounds__(NT, 1)
egnn_kernel(const float* __restrict__ q, const float* __restrict__ x,
            const float* __restrict__ h, const float* __restrict__ e,
            const int* __restrict__ node_mask,
            const float* __restrict__ pq, const float* __restrict__ px,
            const float* __restrict__ pe, const float* __restrict__ ph,
            const int* __restrict__ pmask,
            const float* __restrict__ Wm1, const float* __restrict__ bm1,
            const float* __restrict__ Wm2, const float* __restrict__ bm2,
            const float* __restrict__ Wf1, const float* __restrict__ bf1,
            const float* __restrict__ Wf2, const float* __restrict__ bf2,
            const float* __restrict__ Wx1, const float* __restrict__ bx1,
            const float* __restrict__ Wx2, const float* __restrict__ bx2,
            const float* __restrict__ Wq1, const float* __restrict__ bq1,
            const float* __restrict__ Wq2, const float* __restrict__ bq2,
            const float* __restrict__ Wt1, const float* __restrict__ bt1,
            const float* __restrict__ Wt2, const float* __restrict__ bt2,
            float* __restrict__ out)
{
    extern __shared__ float smem_raw[];
    Smem* s = (Smem*)smem_raw;
    const int i = blockIdx.x;
    const int b = blockIdx.y;
    const int tid = threadIdx.x;

    // ---- stage weights (vectorized) & node-i data ----
    {
        const float4* g4 = (const float4*)(Wm1 + 64 * 64);
        float4* s4 = (float4*)s->Wm1;
        for (int idx = tid; idx < 105 * 16; idx += NT) s4[idx] = g4[idx];
        for (int idx = tid; idx < 7 * 16; idx += NT)
            s4[105 * 16 + idx] = make_float4(0.f, 0.f, 0.f, 0.f);
        g4 = (const float4*)Wm2; s4 = (float4*)s->Wm2;
        for (int idx = tid; idx < 1024; idx += NT) s4[idx] = g4[idx];
        g4 = (const float4*)Wx1; s4 = (float4*)s->Wx1;
        for (int idx = tid; idx < 1024; idx += NT) s4[idx] = g4[idx];
        g4 = (const float4*)Wx2; s4 = (float4*)s->Wx2;
        for (int idx = tid; idx < 48; idx += NT) s4[idx] = g4[idx];
    }
    if (tid < 64) {
        s->bm2[tid] = bm2[tid];
        s->bx1[tid] = bx1[tid];
        s->hi[tid] = h[(b * Nn + i) * 64 + tid];
    }
    if (tid < 3) s->bx2[tid] = bx2[tid];
    if (tid < 4) s->qi[tid] = q[(b * Nn + i) * 4 + tid];
    if (tid < 3) s->xi[tid] = x[(b * Nn + i) * 3 + tid];
    if (tid == 0) s->nn = -1.0f;  // n_neigh has a -1 term
    __syncthreads();

    // n_neigh = sum(node_mask[b]) + sum(pocket_mask[b]) - 1
    {
        float cnt = 0.0f;
        for (int jj = tid; jj < Nn; jj += NT) cnt += node_mask[b * Nn + jj] ? 1.0f : 0.0f;
        for (int jj = tid; jj < Pp; jj += NT) cnt += pmask[b * Pp + jj] ? 1.0f : 0.0f;
        #pragma unroll
        for (int off = 16; off; off >>= 1) cnt += __shfl_down_sync(0xffffffff, cnt, off);
        if ((tid & 31) == 0) atomicAdd(&s->nn, cnt);
    }
    // hoisted bias: bm1h = bm1 + hi @ Wm1[0:64]
    if (tid < 64) {
        float acc = bm1[tid];
        #pragma unroll 4
        for (int k = 0; k < 64; k++) acc += s->hi[k] * Wm1[k * 64 + tid];
        s->bm1h[tid] = acc;
    }
    __syncthreads();

    const float qiw = s->qi[0], qix = s->qi[1], qiy = s->qi[2], qiz = s->qi[3];
    const float xi0 = s->xi[0], xi1 = s->xi[1], xi2 = s->xi[2];
    const int mi = node_mask[b * Nn + i];

    const int jb = tid >> 4;      // 0..31 -> block of 4 j rows
    const int cb = tid & 15;      // 0..15 -> block of 4 output cols
    float* const mb = s->feat;    // m overlay (stride HS)

    // hoisted Wx2 columns for this thread (u = cb*4..cb*4+3) + bx2
    float wx2v[4][3];
    #pragma unroll
    for (int c2 = 0; c2 < 4; c2++)
        #pragma unroll
        for (int cc = 0; cc < 3; cc++)
            wx2v[c2][cc] = s->Wx2[(cb * 4 + c2) * 3 + cc];
    const float bx20 = s->bx2[0], bx21 = s->bx2[1], bx22 = s->bx2[2];

    float4 msum_p = make_float4(0.f, 0.f, 0.f, 0.f);  // cols cb*4..+3, accumulated
    float xacc0 = 0.0f, xacc1 = 0.0f, xacc2 = 0.0f;   // lanes cb<4: row jb*4+cb

    for (int tile = 0; tile < NTILE; tile++) {
        const int j0 = tile * TJ;
        __syncthreads();   // prev tile's reads of feat/m/rotq/maskj complete

        // ---------- Phase A: build feature tile (hj | e | geom | pad) ----------
        for (int idx = tid; idx < TJ * 16; idx += NT) {
            int row = idx >> 4, c = idx & 15;
            int j = j0 + row;
            const float4* hrow = (j < Nn) ? (const float4*)&h[(b * Nn + j) * 64]
                                          : (const float4*)&ph[(b * Pp + (j - Nn)) * 64];
            *(float4*)&s->feat[row * FfP + c * 4] = hrow[c];
        }
        for (int idx = tid; idx < TJ * 8; idx += NT) {
            int row = idx >> 3, c = idx & 7;
            int j = j0 + row;
            const float4* erow = (j < Nn)
                ? (const float4*)&e[((size_t)(b * Nn + i) * Nn + j) * Ee]
                : (const float4*)&pe[((size_t)(b * Nn + i) * Pp + (j - Nn)) * Ee];
            *(float4*)&s->feat[row * FfP + 64 + c * 4] = erow[c];
        }
        if (tid < TJ) {
            int j = j0 + tid;
            float qjw, qjx, qjy, qjz, xj0, xj1, xj2;
            int mj;
            if (j < Nn) {
                const float* qp = &q[(b * Nn + j) * 4];
                qjw = qp[0]; qjx = qp[1]; qjy = qp[2]; qjz = qp[3];
                const float* xp = &x[(b * Nn + j) * 3];
                xj0 = xp[0]; xj1 = xp[1]; xj2 = xp[2];
                mj = (node_mask[b * Nn + j] && (j != i)) ? 1 : 0;
            } else {
                int jp = j - Nn;
                const float* qp = &pq[(b * Pp + jp) * 4];
                qjw = qp[0]; qjx = qp[1]; qjy = qp[2]; qjz = qp[3];
                const float* xp = &px[(b * Pp + jp) * 3];
                xj0 = xp[0]; xj1 = xp[1]; xj2 = xp[2];
                mj = pmask[b * Pp + jp] ? 1 : 0;
            }
            s->maskj[tid] = (mi && mj) ? 1.0f : 0.0f;

            float d0 = xi0 - xj0, d1 = xi1 - xj1, dz = xi2 - xj2;
            float dd = d0 * d0 + d1 * d1 + dz * dz;
            float qd = fabsf(qiw * qjw + qix * qjx + qiy * qjy + qiz * qjz);
            float vx = -qjx, vy = -qjy, vz = -qjz;      // conj_j vector part
            float tx = 2.0f * (vy * dz - vz * d1);
            float ty = 2.0f * (vz * d0 - vx * dz);
            float tz = 2.0f * (vx * d1 - vy * d0);
            float lx0 = d0 + qjw * tx + (vy * tz - vz * ty);
            float lx1 = d1 + qjw * ty + (vz * tx - vx * tz);
            float lx2 = dz + qjw * tz + (vx * ty - vy * tx);
            float lq0 = qjw * qiw - vx * qix - vy * qiy - vz * qiz;
            float lq1 = qjw * qix + vx * qiw + vy * qiz - vz * qiy;
            float lq2 = qjw * qiy - vx * qiz + vy * qiw + vz * qix;
            float lq3 = qjw * qiz + vx * qiy - vy * qix + vz * qiw;
            float* fr = &s->feat[tid * FfP + 96];
            fr[0] = lx0; fr[1] = lx1; fr[2] = lx2;
            fr[3] = lq0; fr[4] = lq1; fr[5] = lq2; fr[6] = lq3;
            fr[7] = dd; fr[8] = qd;
            fr[9] = 0.0f; fr[10] = 0.0f; fr[11] = 0.0f;
            fr[12] = 0.0f; fr[13] = 0.0f; fr[14] = 0.0f; fr[15] = 0.0f;
            float qn = fmaxf(sqrtf(qjw * qjw + qjx * qjx + qjy * qjy + qjz * qjz), 1e-12f);
            float inv = 1.0f / qn;
            s->rotq[tid * 4 + 0] = qjw * inv;
            s->rotq[tid * 4 + 1] = qjx * inv;
            s->rotq[tid * 4 + 2] = qjy * inv;
            s->rotq[tid * 4 + 3] = qjz * inv;
        }
        __syncthreads();

        // ---------- Phase B: hid = relu(feat @ Wm1[64:] + bm1h) ----------
        {
            float acc[4][4] = {};
            gemm16<FfP / 4, FfP>(&s->feat[(jb * 4) * FfP], &s->Wm1[cb * 4], acc);
            float4 bb = *(const float4*)&s->bm1h[cb * 4];
            float* hr = &s->hid[(jb * 4) * HS + cb * 4];
            #pragma unroll
            for (int r = 0; r < 4; r++) {
                float4 o;
                o.x = fmaxf(acc[r][0] + bb.x, 0.0f);
                o.y = fmaxf(acc[r][1] + bb.y, 0.0f);
                o.z = fmaxf(acc[r][2] + bb.z, 0.0f);
                o.w = fmaxf(acc[r][3] + bb.w, 0.0f);
                *(float4*)(hr + r * HS) = o;
            }
        }
        __syncwarp();   // writers == readers: same 16-thread group

        // ---------- Phase C: m = (hid @ Wm2 + bm2) * mask ; msum in regs ----------
        {
            float acc[4][4] = {};
            gemm16<16, HS>(&s->hid[(jb * 4) * HS], &s->Wm2[cb * 4], acc);
            float4 bb = *(const float4*)&s->bm2[cb * 4];
            float* mr = &mb[(jb * 4) * HS + cb * 4];
            #pragma unroll
            for (int r = 0; r < 4; r++) {
                float mk = s->maskj[jb * 4 + r];
                float4 o;
                o.x = (acc[r][0] + bb.x) * mk;
                o.y = (acc[r][1] + bb.y) * mk;
                o.z = (acc[r][2] + bb.z) * mk;
                o.w = (acc[r][3] + bb.w) * mk;
                *(float4*)(mr + r * HS) = o;
                msum_p.x += o.x; msum_p.y += o.y;
                msum_p.z += o.z; msum_p.w += o.w;
            }
        }
        __syncwarp();

        // ---------- Phase D: hid2 = relu(m @ Wx1 + bx1) -> registers ----------
        float d2[4][4];
        {
            float acc[4][4] = {};
            gemm16<16, HS>(&mb[(jb * 4) * HS], &s->Wx1[cb * 4], acc);
            float4 bb = *(const float4*)&s->bx1[cb * 4];
            #pragma unroll
            for (int r = 0; r < 4; r++) {
                d2[r][0] = fmaxf(acc[r][0] + bb.x, 0.0f);
                d2[r][1] = fmaxf(acc[r][1] + bb.y, 0.0f);
                d2[r][2] = fmaxf(acc[r][2] + bb.z, 0.0f);
                d2[r][3] = fmaxf(acc[r][3] + bb.w, 0.0f);
            }
        }

        // ---------- Phase E: dx partials -> 16-lane bfly reduce -> rotate ----------
        {
            float p[4][3];
            #pragma unroll
            for (int r = 0; r < 4; r++) {
                #pragma unroll
                for (int cc = 0; cc < 3; cc++) {
                    p[r][cc] = d2[r][0] * wx2v[0][cc] + d2[r][1] * wx2v[1][cc]
                             + d2[r][2] * wx2v[2][cc] + d2[r][3] * wx2v[3][cc];
                }
            }
            #pragma unroll
            for (int mskp = 1; mskp < 16; mskp <<= 1) {
                #pragma unroll
                for (int r = 0; r < 4; r++) {
                    #pragma unroll
                    for (int cc = 0; cc < 3; cc++)
                        p[r][cc] += __shfl_xor_sync(0xffffffffu, p[r][cc], mskp);
                }
            }
            if (cb < 4) {
                float a0, a1, a2;
                if      (cb == 0) { a0 = p[0][0]; a1 = p[0][1]; a2 = p[0][2]; }
                else if (cb == 1) { a0 = p[1][0]; a1 = p[1][1]; a2 = p[1][2]; }
                else if (cb == 2) { a0 = p[2][0]; a1 = p[2][1]; a2 = p[2][2]; }
                else              { a0 = p[3][0]; a1 = p[3][1]; a2 = p[3][2]; }
                int row = jb * 4 + cb;
                float mk = s->maskj[row];
                a0 = (a0 + bx20) * mk;
                a1 = (a1 + bx21) * mk;
                a2 = (a2 + bx22) * mk;
                float w  = s->rotq[row * 4 + 0];
                float vx = s->rotq[row * 4 + 1];
                float vy = s->rotq[row * 4 + 2];
                float vz = s->rotq[row * 4 + 3];
                float tx = 2.0f * (vy * a2 - vz * a1);
                float ty = 2.0f * (vz * a0 - vx * a2);
                float tz = 2.0f * (vx * a1 - vy * a0);
                xacc0 += a0 + w * tx + (vy * tz - vz * ty);
                xacc1 += a1 + w * ty + (vz * tx - vx * tz);
                xacc2 += a2 + w * tz + (vx * ty - vy * tx);
            }
        }
    }

    // ---- write per-thread partials, reduce ----
    __syncthreads();
    {
        float* mp = &s->msum_part[jb * 64 + cb * 4];
        mp[0] = msum_p.x; mp[1] = msum_p.y; mp[2] = msum_p.z; mp[3] = msum_p.w;
    }
    if (cb < 4) {
        int row = jb * 4 + cb;
        s->xpart[row * 3 + 0] = xacc0;
        s->xpart[row * 3 + 1] = xacc1;
        s->xpart[row * 3 + 2] = xacc2;
    }
    __syncthreads();
    if (tid < 64) {
        float acc = 0.0f;
        #pragma unroll 4
        for (int g = 0; g < 32; g++) acc += s->msum_part[g * 64 + tid];
        s->msum[tid] = acc;
    }
    __syncthreads();

    const int grp = tid >> 6, lt = tid & 63;
    // ---- epilogue hidden layers + xacc reduce ----
    if (grp == 0) {
        float acc = bf1[lt];
        #pragma unroll 4
        for (int k = 0; k < 64; k++) acc += s->hi[k] * Wf1[k * 64 + lt];
        #pragma unroll 4
        for (int k = 0; k < 64; k++) acc += s->msum[k] * Wf1[(64 + k) * 64 + lt];
        s->hidf[lt] = fmaxf(acc, 0.0f);
    } else if (grp == 1) {
        float acc = bt1[lt];
        #pragma unroll 4
        for (int k = 0; k < 64; k++) acc += s->msum[k] * Wt1[k * 64 + lt];
        s->hidt[lt] = fmaxf(acc, 0.0f);
    } else if (grp == 2) {
        float acc = bq1[lt];
        #pragma unroll 4
        for (int k = 0; k < 64; k++) acc += s->msum[k] * Wq1[k * 64 + lt];
        s->hidq[lt] = fmaxf(acc, 0.0f);
    } else if (grp == 3 && lt < 3) {
        float sum = 0.0f;
        #pragma unroll 4
        for (int j = 0; j < TJ; j++) sum += s->xpart[j * 3 + lt];
        s->xacc[lt] = sum;
    }
    __syncthreads();

    float* out_q = out;
    float* out_x = out + Bb * Nn * 4;
    float* out_t = out + Bb * Nn * 7;
    float* out_o = out + Bb * Nn * 21;
    const int node = b * Nn + i;

    if (grp == 0) {
        float acc = bf2[lt];
        #pragma unroll 4
        for (int u = 0; u < 64; u++) acc += s->hidf[u] * Wf2[u * 64 + lt];
        out_o[node * 64 + lt] = acc;
    } else if (grp == 1 && lt < 14) {
        float acc = bt2[lt];
        #pragma unroll 4
        for (int u = 0; u < 64; u++) acc += s->hidt[u] * Wt2[u * 14 + lt];
        s->traw[lt] = acc;
    } else if (grp == 2 && lt < 4) {
        float acc = bq2[lt];
        #pragma unroll 4
        for (int u = 0; u < 64; u++) acc += s->hidq[u] * Wq2[u * 4 + lt];
        s->dqraw[lt] = acc;
    }
    __syncthreads();

    if (tid == 0) {
        float d0 = s->dqraw[0], d1 = s->dqraw[1], d2v = s->dqraw[2], d3 = s->dqraw[3];
        if (!mi) { d0 = 1.0f; d1 = 0.0f; d2v = 0.0f; d3 = 0.0f; }
        float nrm = fmaxf(sqrtf(d0 * d0 + d1 * d1 + d2v * d2v + d3 * d3), 1e-12f);
        float inv = 1.0f / nrm;
        d0 *= inv; d1 *= inv; d2v *= inv; d3 *= inv;
        float u0 = qiw * d0 - qix * d1 - qiy * d2v - qiz * d3;
        float u1 = qiw * d1 + qix * d0 + qiy * d3 - qiz * d2v;
        float u2 = qiw * d2v - qix * d3 + qiy * d0 + qiz * d1;
        float u3 = qiw * d3 + qix * d2v - qiy * d1 + qiz * d0;
        if (!mi) { u0 = 1.0f; u1 = 0.0f; u2 = 0.0f; u3 = 0.0f; }
        nrm = fmaxf(sqrtf(u0 * u0 + u1 * u1 + u2 * u2 + u3 * u3), 1e-12f);
        inv = 1.0f / nrm;
        out_q[node * 4 + 0] = u0 * inv;
        out_q[node * 4 + 1] = u1 * inv;
        out_q[node * 4 + 2] = u2 * inv;
        out_q[node * 4 + 3] = u3 * inv;
    }
    if (tid >= 4 && tid < 7) {
        int c = tid - 4;
        out_x[node * 3 + c] = s->xi[c] + s->xacc[c] / s->nn;
    }
    if (tid >= 32 && tid < 39) {
        int p = tid - 32;
        float a = s->traw[p * 2 + 0];
        float c = s->traw[p * 2 + 1];
        float nrm = fmaxf(sqrtf(a * a + c * c), 1e-12f);
        out_t[node * 14 + p * 2 + 0] = a / nrm;
        out_t[node * 14 + p * 2 + 1] = c / nrm;
    }
}

extern "C" void kernel_launch(void* const* d_in, const int* in_sizes, int n_in,
                              void* d_out, int out_size)
{
    const float* q  = (const float*)d_in[0];
    const float* x  = (const float*)d_in[1];
    // d_in[2] = torsions (values unused)
    const float* h  = (const float*)d_in[3];
    const float* e  = (const float*)d_in[4];
    const int* node_mask = (const int*)d_in[5];
    const float* pq = (const float*)d_in[6];
    const float* px = (const float*)d_in[7];
    const float* pe = (const float*)d_in[8];
    const float* ph = (const float*)d_in[9];
    const int* pmask = (const int*)d_in[10];
    const float* Wm1 = (const float*)d_in[11];
    const float* bm1 = (const float*)d_in[12];
    const float* Wm2 = (const float*)d_in[13];
    const float* bm2 = (const float*)d_in[14];
    const float* Wf1 = (const float*)d_in[15];
    const float* bf1 = (const float*)d_in[16];
    const float* Wf2 = (const float*)d_in[17];
    const float* bf2 = (const float*)d_in[18];
    const float* Wx1 = (const float*)d_in[19];
    const float* bx1 = (const float*)d_in[20];
    const float* Wx2 = (const float*)d_in[21];
    const float* bx2 = (const float*)d_in[22];
    const float* Wq1 = (const float*)d_in[23];
    const float* bq1 = (const float*)d_in[24];
    const float* Wq2 = (const float*)d_in[25];
    const float* bq2 = (const float*)d_in[26];
    const float* Wt1 = (const float*)d_in[27];
    const float* bt1 = (const float*)d_in[28];
    const float* Wt2 = (const float*)d_in[29];
    const float* bt2 = (const float*)d_in[30];

    const size_t smem = sizeof(Smem);
    cudaFuncSetAttribute(egnn_kernel, cudaFuncAttributeMaxDynamicSharedMemorySize,
                         (int)smem);

    dim3 grid(Nn, Bb);
    egnn_kernel<<<grid, NT, smem>>>(
        q, x, h, e, node_mask, pq, px, pe, ph, pmask,
        Wm1, bm1, Wm2, bm2, Wf1, bf1, Wf2, bf2,
        Wx1, bx1, Wx2, bx2, Wq1, bq1, Wq2, bq2, Wt1, bt1, Wt2, bt2,
        (float*)d_out);
}

// round 10
// speedup vs baseline: 2.5709x; 1.2044x over previous
#include <cuda_runtime.h>
#include <math.h>

#define Bb 4
#define Nn 128
#define Pp 512
#define Ee 32
#define NJt 640         // n + p
#define FfB 44          // Phase-B feat row: 32 e + 9 geom + 3 pad
#define TJ 128          // j-tile rows
#define NTILE 5         // 640 / 128
#define HS 68           // hid/m row stride (floats, mult of 4)
#define NT 512          // threads per CTA

__device__ float g_hjproj[Bb * NJt * 64];   // h_all[b,j] @ Wm1[64:128]

struct __align__(16) Smem {
    float Wm1[FfB * 64];   // rows 0..40 = Wm1[128..168], rows 41..43 zero
    float Wm2[64 * 64];
    float Wx1[64 * 64];
    float Wx2[64 * 3];
    float bm1h[64];        // bm1 + hi @ Wm1[0:64]
    float bm2[64];
    float bx1[64];
    float bx2[4];
    float feat[TJ * FfB];  // 128 x 44
    float hid[TJ * HS];    // 128 x 68
    float mbuf[TJ * HS];   // 128 x 68
    float hi[64];
    float maskj[TJ];
    float rotq[TJ * 4];
    float msum_part[32 * 64];
    float xpart[TJ * 3];
    float msum[64];
    float hidf[64];
    float hidt[64];
    float hidq[64];
    float traw[16];
    float dqraw[4];
    float xacc[4];
    float qi[4];
    float xi[4];
    float nn;
};

#define RANK1(CMP_, WV_) \
    acc[0][0] += a0.CMP_ * WV_.x; acc[0][1] += a0.CMP_ * WV_.y; acc[0][2] += a0.CMP_ * WV_.z; acc[0][3] += a0.CMP_ * WV_.w; \
    acc[1][0] += a1.CMP_ * WV_.x; acc[1][1] += a1.CMP_ * WV_.y; acc[1][2] += a1.CMP_ * WV_.z; acc[1][3] += a1.CMP_ * WV_.w; \
    acc[2][0] += a2.CMP_ * WV_.x; acc[2][1] += a2.CMP_ * WV_.y; acc[2][2] += a2.CMP_ * WV_.z; acc[2][3] += a2.CMP_ * WV_.w; \
    acc[3][0] += a3.CMP_ * WV_.x; acc[3][1] += a3.CMP_ * WV_.y; acc[3][2] += a3.CMP_ * WV_.z; acc[3][3] += a3.CMP_ * WV_.w;

template<int KVCOUNT, int SSTRIDE>
__device__ __forceinline__ void gemm16(const float* __restrict__ src,
                                       const float* __restrict__ wcol,
                                       float acc[4][4])
{
    #pragma unroll 2
    for (int kv = 0; kv < KVCOUNT; kv++) {
        float4 a0 = *(const float4*)(src + 0 * SSTRIDE + kv * 4);
        float4 a1 = *(const float4*)(src + 1 * SSTRIDE + kv * 4);
        float4 a2 = *(const float4*)(src + 2 * SSTRIDE + kv * 4);
        float4 a3 = *(const float4*)(src + 3 * SSTRIDE + kv * 4);
        float4 w0 = *(const float4*)(wcol + (kv * 4 + 0) * 64);
        float4 w1 = *(const float4*)(wcol + (kv * 4 + 1) * 64);
        float4 w2 = *(const float4*)(wcol + (kv * 4 + 2) * 64);
        float4 w3 = *(const float4*)(wcol + (kv * 4 + 3) * 64);
        RANK1(x, w0)
        RANK1(y, w1)
        RANK1(z, w2)
        RANK1(w, w3)
    }
}

// ---- prologue: hjproj[b,j,:] = h_all[b,j,:] @ Wm1[64:128,:] ----
__global__ void __launch_bounds__(256)
hjproj_kernel(const float* __restrict__ h, const float* __restrict__ ph,
              const float* __restrict__ Wm1)
{
    __shared__ float sh[64 * 64];
    __shared__ float sw[64 * 64];
    const int j0 = blockIdx.x * 64;
    const int b = blockIdx.y;
    const int tid = threadIdx.x;

    {
        const float4* g4 = (const float4*)(Wm1 + 64 * 64);
        float4* s4 = (float4*)sw;
        for (int idx = tid; idx < 1024; idx += 256) s4[idx] = g4[idx];
    }
    for (int idx = tid; idx < 64 * 16; idx += 256) {
        int row = idx >> 4, c = idx & 15;
        int j = j0 + row;
        const float4* hrow = (j < Nn) ? (const float4*)&h[(b * Nn + j) * 64]
                                      : (const float4*)&ph[(b * Pp + (j - Nn)) * 64];
        *(float4*)&sh[row * 64 + c * 4] = hrow[c];
    }
    __syncthreads();

    int row = tid >> 2;         // 0..63
    int cq = tid & 3;           // 0..3 -> 16 cols
    float acc[16] = {};
    #pragma unroll 4
    for (int k = 0; k < 64; k++) {
        float hv = sh[row * 64 + k];
        const float* wr = &sw[k * 64 + cq * 16];
        #pragma unroll
        for (int c = 0; c < 16; c++) acc[c] += hv * wr[c];
    }
    float4* op = (float4*)&g_hjproj[((size_t)(b * NJt) + j0 + row) * 64 + cq * 16];
    op[0] = make_float4(acc[0], acc[1], acc[2], acc[3]);
    op[1] = make_float4(acc[4], acc[5], acc[6], acc[7]);
    op[2] = make_float4(acc[8], acc[9], acc[10], acc[11]);
    op[3] = make_float4(acc[12], acc[13], acc[14], acc[15]);
}

__global__ void __launch_bounds__(NT, 1)
egnn_kernel(const float* __restrict__ q, const float* __restrict__ x,
            const float* __restrict__ h, const float* __restrict__ e,
            const int* __restrict__ node_mask,
            const float* __restrict__ pq, const float* __restrict__ px,
            const float* __restrict__ pe, const float* __restrict__ ph,
            const int* __restrict__ pmask,
            const float* __restrict__ Wm1, const float* __restrict__ bm1,
            const float* __restrict__ Wm2, const float* __restrict__ bm2,
            const float* __restrict__ Wf1, const float* __restrict__ bf1,
            const float* __restrict__ Wf2, const float* __restrict__ bf2,
            const float* __restrict__ Wx1, const float* __restrict__ bx1,
            const float* __restrict__ Wx2, const float* __restrict__ bx2,
            const float* __restrict__ Wq1, const float* __restrict__ bq1,
            const float* __restrict__ Wq2, const float* __restrict__ bq2,
            const float* __restrict__ Wt1, const float* __restrict__ bt1,
            const float* __restrict__ Wt2, const float* __restrict__ bt2,
            float* __restrict__ out)
{
    extern __shared__ float smem_raw[];
    Smem* s = (Smem*)smem_raw;
    const int i = blockIdx.x;
    const int b = blockIdx.y;
    const int tid = threadIdx.x;

    // ---- stage weights & node-i data ----
    {
        // Wm1 rows 128..168 -> smem rows 0..40 ; rows 41..43 zero
        const float4* g4 = (const float4*)(Wm1 + 128 * 64);
        float4* s4 = (float4*)s->Wm1;
        for (int idx = tid; idx < 41 * 16; idx += NT) s4[idx] = g4[idx];
        for (int idx = tid; idx < 3 * 16; idx += NT)
            s4[41 * 16 + idx] = make_float4(0.f, 0.f, 0.f, 0.f);
        g4 = (const float4*)Wm2; s4 = (float4*)s->Wm2;
        for (int idx = tid; idx < 1024; idx += NT) s4[idx] = g4[idx];
        g4 = (const float4*)Wx1; s4 = (float4*)s->Wx1;
        for (int idx = tid; idx < 1024; idx += NT) s4[idx] = g4[idx];
        g4 = (const float4*)Wx2; s4 = (float4*)s->Wx2;
        for (int idx = tid; idx < 48; idx += NT) s4[idx] = g4[idx];
    }
    if (tid < 64) {
        s->bm2[tid] = bm2[tid];
        s->bx1[tid] = bx1[tid];
        s->hi[tid] = h[(b * Nn + i) * 64 + tid];
    }
    if (tid < 3) s->bx2[tid] = bx2[tid];
    if (tid < 4) s->qi[tid] = q[(b * Nn + i) * 4 + tid];
    if (tid < 3) s->xi[tid] = x[(b * Nn + i) * 3 + tid];
    if (tid == 0) s->nn = -1.0f;
    __syncthreads();

    // n_neigh
    {
        float cnt = 0.0f;
        for (int jj = tid; jj < Nn; jj += NT) cnt += node_mask[b * Nn + jj] ? 1.0f : 0.0f;
        for (int jj = tid; jj < Pp; jj += NT) cnt += pmask[b * Pp + jj] ? 1.0f : 0.0f;
        #pragma unroll
        for (int off = 16; off; off >>= 1) cnt += __shfl_down_sync(0xffffffff, cnt, off);
        if ((tid & 31) == 0) atomicAdd(&s->nn, cnt);
    }
    // hoisted bias: bm1h = bm1 + hi @ Wm1[0:64]
    if (tid < 64) {
        float acc = bm1[tid];
        #pragma unroll 4
        for (int k = 0; k < 64; k++) acc += s->hi[k] * Wm1[k * 64 + tid];
        s->bm1h[tid] = acc;
    }
    __syncthreads();

    const float qiw = s->qi[0], qix = s->qi[1], qiy = s->qi[2], qiz = s->qi[3];
    const float xi0 = s->xi[0], xi1 = s->xi[1], xi2 = s->xi[2];
    const int mi = node_mask[b * Nn + i];

    const int jb = tid >> 4;      // 0..31 -> block of 4 j rows
    const int cb = tid & 15;      // 0..15 -> block of 4 output cols
    float* const mb = s->mbuf;

    float wx2v[4][3];
    #pragma unroll
    for (int c2 = 0; c2 < 4; c2++)
        #pragma unroll
        for (int cc = 0; cc < 3; cc++)
            wx2v[c2][cc] = s->Wx2[(cb * 4 + c2) * 3 + cc];
    const float bx20 = s->bx2[0], bx21 = s->bx2[1], bx22 = s->bx2[2];

    float4 msum_p = make_float4(0.f, 0.f, 0.f, 0.f);
    float xacc0 = 0.0f, xacc1 = 0.0f, xacc2 = 0.0f;

    const float* hjp_base = &g_hjproj[(size_t)b * NJt * 64 + cb * 4];

    for (int tile = 0; tile < NTILE; tile++) {
        const int j0 = tile * TJ;
        __syncthreads();

        // ---------- Phase A: build feature tile (e | geom | pad) ----------
        for (int idx = tid; idx < TJ * 8; idx += NT) {
            int row = idx >> 3, c = idx & 7;
            int j = j0 + row;
            const float4* erow = (j < Nn)
                ? (const float4*)&e[((size_t)(b * Nn + i) * Nn + j) * Ee]
                : (const float4*)&pe[((size_t)(b * Nn + i) * Pp + (j - Nn)) * Ee];
            *(float4*)&s->feat[row * FfB + c * 4] = erow[c];
        }
        if (tid < TJ) {
            int j = j0 + tid;
            float qjw, qjx, qjy, qjz, xj0, xj1, xj2;
            int mj;
            if (j < Nn) {
                const float* qp = &q[(b * Nn + j) * 4];
                qjw = qp[0]; qjx = qp[1]; qjy = qp[2]; qjz = qp[3];
                const float* xp = &x[(b * Nn + j) * 3];
                xj0 = xp[0]; xj1 = xp[1]; xj2 = xp[2];
                mj = (node_mask[b * Nn + j] && (j != i)) ? 1 : 0;
            } else {
                int jp = j - Nn;
                const float* qp = &pq[(b * Pp + jp) * 4];
                qjw = qp[0]; qjx = qp[1]; qjy = qp[2]; qjz = qp[3];
                const float* xp = &px[(b * Pp + jp) * 3];
                xj0 = xp[0]; xj1 = xp[1]; xj2 = xp[2];
                mj = pmask[b * Pp + jp] ? 1 : 0;
            }
            s->maskj[tid] = (mi && mj) ? 1.0f : 0.0f;

            float d0 = xi0 - xj0, d1 = xi1 - xj1, dz = xi2 - xj2;
            float dd = d0 * d0 + d1 * d1 + dz * dz;
            float qd = fabsf(qiw * qjw + qix * qjx + qiy * qjy + qiz * qjz);
            float vx = -qjx, vy = -qjy, vz = -qjz;
            float tx = 2.0f * (vy * dz - vz * d1);
            float ty = 2.0f * (vz * d0 - vx * dz);
            float tz = 2.0f * (vx * d1 - vy * d0);
            float lx0 = d0 + qjw * tx + (vy * tz - vz * ty);
            float lx1 = d1 + qjw * ty + (vz * tx - vx * tz);
            float lx2 = dz + qjw * tz + (vx * ty - vy * tx);
            float lq0 = qjw * qiw - vx * qix - vy * qiy - vz * qiz;
            float lq1 = qjw * qix + vx * qiw + vy * qiz - vz * qiy;
            float lq2 = qjw * qiy - vx * qiz + vy * qiw + vz * qix;
            float lq3 = qjw * qiz + vx * qiy - vy * qix + vz * qiw;
            float* fr = &s->feat[tid * FfB + 32];
            fr[0] = lx0; fr[1] = lx1; fr[2] = lx2;
            fr[3] = lq0; fr[4] = lq1; fr[5] = lq2; fr[6] = lq3;
            fr[7] = dd; fr[8] = qd;
            fr[9] = 0.0f; fr[10] = 0.0f; fr[11] = 0.0f;  // pad 41..43
            float qn = fmaxf(sqrtf(qjw * qjw + qjx * qjx + qjy * qjy + qjz * qjz), 1e-12f);
            float inv = 1.0f / qn;
            s->rotq[tid * 4 + 0] = qjw * inv;
            s->rotq[tid * 4 + 1] = qjx * inv;
            s->rotq[tid * 4 + 2] = qjy * inv;
            s->rotq[tid * 4 + 3] = qjz * inv;
        }
        __syncthreads();

        // ---------- Phase B: hid = relu(featB @ Wm1[128:] + bm1h + hjproj[j]) ----------
        {
            // prefetch hjproj rows (global, L2-resident) to overlap with GEMM
            const float* hp = hjp_base + (size_t)(j0 + jb * 4) * 64;
            float4 hp0 = *(const float4*)(hp + 0 * 64);
            float4 hp1 = *(const float4*)(hp + 1 * 64);
            float4 hp2 = *(const float4*)(hp + 2 * 64);
            float4 hp3 = *(const float4*)(hp + 3 * 64);

            float acc[4][4] = {};
            gemm16<FfB / 4, FfB>(&s->feat[(jb * 4) * FfB], &s->Wm1[cb * 4], acc);
            float4 bb = *(const float4*)&s->bm1h[cb * 4];
            float* hr = &s->hid[(jb * 4) * HS + cb * 4];
            float4 o;
            o.x = fmaxf(acc[0][0] + bb.x + hp0.x, 0.0f);
            o.y = fmaxf(acc[0][1] + bb.y + hp0.y, 0.0f);
            o.z = fmaxf(acc[0][2] + bb.z + hp0.z, 0.0f);
            o.w = fmaxf(acc[0][3] + bb.w + hp0.w, 0.0f);
            *(float4*)(hr + 0 * HS) = o;
            o.x = fmaxf(acc[1][0] + bb.x + hp1.x, 0.0f);
            o.y = fmaxf(acc[1][1] + bb.y + hp1.y, 0.0f);
            o.z = fmaxf(acc[1][2] + bb.z + hp1.z, 0.0f);
            o.w = fmaxf(acc[1][3] + bb.w + hp1.w, 0.0f);
            *(float4*)(hr + 1 * HS) = o;
            o.x = fmaxf(acc[2][0] + bb.x + hp2.x, 0.0f);
            o.y = fmaxf(acc[2][1] + bb.y + hp2.y, 0.0f);
            o.z = fmaxf(acc[2][2] + bb.z + hp2.z, 0.0f);
            o.w = fmaxf(acc[2][3] + bb.w + hp2.w, 0.0f);
            *(float4*)(hr + 2 * HS) = o;
            o.x = fmaxf(acc[3][0] + bb.x + hp3.x, 0.0f);
            o.y = fmaxf(acc[3][1] + bb.y + hp3.y, 0.0f);
            o.z = fmaxf(acc[3][2] + bb.z + hp3.z, 0.0f);
            o.w = fmaxf(acc[3][3] + bb.w + hp3.w, 0.0f);
            *(float4*)(hr + 3 * HS) = o;
        }
        __syncwarp();

        // ---------- Phase C: m = (hid @ Wm2 + bm2) * mask ; msum in regs ----------
        {
            float acc[4][4] = {};
            gemm16<16, HS>(&s->hid[(jb * 4) * HS], &s->Wm2[cb * 4], acc);
            float4 bb = *(const float4*)&s->bm2[cb * 4];
            float* mr = &mb[(jb * 4) * HS + cb * 4];
            #pragma unroll
            for (int r = 0; r < 4; r++) {
                float mk = s->maskj[jb * 4 + r];
                float4 o;
                o.x = (acc[r][0] + bb.x) * mk;
                o.y = (acc[r][1] + bb.y) * mk;
                o.z = (acc[r][2] + bb.z) * mk;
                o.w = (acc[r][3] + bb.w) * mk;
                *(float4*)(mr + r * HS) = o;
                msum_p.x += o.x; msum_p.y += o.y;
                msum_p.z += o.z; msum_p.w += o.w;
            }
        }
        __syncwarp();

        // ---------- Phase D: hid2 = relu(m @ Wx1 + bx1) -> registers ----------
        float d2[4][4];
        {
            float acc[4][4] = {};
            gemm16<16, HS>(&mb[(jb * 4) * HS], &s->Wx1[cb * 4], acc);
            float4 bb = *(const float4*)&s->bx1[cb * 4];
            #pragma unroll
            for (int r = 0; r < 4; r++) {
                d2[r][0] = fmaxf(acc[r][0] + bb.x, 0.0f);
                d2[r][1] = fmaxf(acc[r][1] + bb.y, 0.0f);
                d2[r][2] = fmaxf(acc[r][2] + bb.z, 0.0f);
                d2[r][3] = fmaxf(acc[r][3] + bb.w, 0.0f);
            }
        }

        // ---------- Phase E: dx partials -> 16-lane bfly reduce -> rotate ----------
        {
            float p[4][3];
            #pragma unroll
            for (int r = 0; r < 4; r++) {
                #pragma unroll
                for (int cc = 0; cc < 3; cc++) {
                    p[r][cc] = d2[r][0] * wx2v[0][cc] + d2[r][1] * wx2v[1][cc]
                             + d2[r][2] * wx2v[2][cc] + d2[r][3] * wx2v[3][cc];
                }
            }
            #pragma unroll
            for (int mskp = 1; mskp < 16; mskp <<= 1) {
                #pragma unroll
                for (int r = 0; r < 4; r++) {
                    #pragma unroll
                    for (int cc = 0; cc < 3; cc++)
                        p[r][cc] += __shfl_xor_sync(0xffffffffu, p[r][cc], mskp);
                }
            }
            if (cb < 4) {
                float a0, a1, a2;
                if      (cb == 0) { a0 = p[0][0]; a1 = p[0][1]; a2 = p[0][2]; }
                else if (cb == 1) { a0 = p[1][0]; a1 = p[1][1]; a2 = p[1][2]; }
                else if (cb == 2) { a0 = p[2][0]; a1 = p[2][1]; a2 = p[2][2]; }
                else              { a0 = p[3][0]; a1 = p[3][1]; a2 = p[3][2]; }
                int row = jb * 4 + cb;
                float mk = s->maskj[row];
                a0 = (a0 + bx20) * mk;
                a1 = (a1 + bx21) * mk;
                a2 = (a2 + bx22) * mk;
                float w  = s->rotq[row * 4 + 0];
                float vx = s->rotq[row * 4 + 1];
                float vy = s->rotq[row * 4 + 2];
                float vz = s->rotq[row * 4 + 3];
                float tx = 2.0f * (vy * a2 - vz * a1);
                float ty = 2.0f * (vz * a0 - vx * a2);
                float tz = 2.0f * (vx * a1 - vy * a0);
                xacc0 += a0 + w * tx + (vy * tz - vz * ty);
                xacc1 += a1 + w * ty + (vz * tx - vx * tz);
                xacc2 += a2 + w * tz + (vx * ty - vy * tx);
            }
        }
    }

    // ---- write per-thread partials, reduce ----
    __syncthreads();
    {
        float* mp = &s->msum_part[jb * 64 + cb * 4];
        mp[0] = msum_p.x; mp[1] = msum_p.y; mp[2] = msum_p.z; mp[3] = msum_p.w;
    }
    if (cb < 4) {
        int row = jb * 4 + cb;
        s->xpart[row * 3 + 0] = xacc0;
        s->xpart[row * 3 + 1] = xacc1;
        s->xpart[row * 3 + 2] = xacc2;
    }
    __syncthreads();
    if (tid < 64) {
        float acc = 0.0f;
        #pragma unroll 4
        for (int g = 0; g < 32; g++) acc += s->msum_part[g * 64 + tid];
        s->msum[tid] = acc;
    }
    __syncthreads();

    const int grp = tid >> 6, lt = tid & 63;
    if (grp == 0) {
        float acc = bf1[lt];
        #pragma unroll 4
        for (int k = 0; k < 64; k++) acc += s->hi[k] * Wf1[k * 64 + lt];
        #pragma unroll 4
        for (int k = 0; k < 64; k++) acc += s->msum[k] * Wf1[(64 + k) * 64 + lt];
        s->hidf[lt] = fmaxf(acc, 0.0f);
    } else if (grp == 1) {
        float acc = bt1[lt];
        #pragma unroll 4
        for (int k = 0; k < 64; k++) acc += s->msum[k] * Wt1[k * 64 + lt];
        s->hidt[lt] = fmaxf(acc, 0.0f);
    } else if (grp == 2) {
        float acc = bq1[lt];
        #pragma unroll 4
        for (int k = 0; k < 64; k++) acc += s->msum[k] * Wq1[k * 64 + lt];
        s->hidq[lt] = fmaxf(acc, 0.0f);
    } else if (grp == 3 && lt < 3) {
        float sum = 0.0f;
        #pragma unroll 4
        for (int j = 0; j < TJ; j++) sum += s->xpart[j * 3 + lt];
        s->xacc[lt] = sum;
    }
    __syncthreads();

    float* out_q = out;
    float* out_x = out + Bb * Nn * 4;
    float* out_t = out + Bb * Nn * 7;
    float* out_o = out + Bb * Nn * 21;
    const int node = b * Nn + i;

    if (grp == 0) {
        float acc = bf2[lt];
        #pragma unroll 4
        for (int u = 0; u < 64; u++) acc += s->hidf[u] * Wf2[u * 64 + lt];
        out_o[node * 64 + lt] = acc;
    } else if (grp == 1 && lt < 14) {
        float acc = bt2[lt];
        #pragma unroll 4
        for (int u = 0; u < 64; u++) acc += s->hidt[u] * Wt2[u * 14 + lt];
        s->traw[lt] = acc;
    } else if (grp == 2 && lt < 4) {
        float acc = bq2[lt];
        #pragma unroll 4
        for (int u = 0; u < 64; u++) acc += s->hidq[u] * Wq2[u * 4 + lt];
        s->dqraw[lt] = acc;
    }
    __syncthreads();

    if (tid == 0) {
        float d0 = s->dqraw[0], d1 = s->dqraw[1], d2v = s->dqraw[2], d3 = s->dqraw[3];
        if (!mi) { d0 = 1.0f; d1 = 0.0f; d2v = 0.0f; d3 = 0.0f; }
        float nrm = fmaxf(sqrtf(d0 * d0 + d1 * d1 + d2v * d2v + d3 * d3), 1e-12f);
        float inv = 1.0f / nrm;
        d0 *= inv; d1 *= inv; d2v *= inv; d3 *= inv;
        float u0 = qiw * d0 - qix * d1 - qiy * d2v - qiz * d3;
        float u1 = qiw * d1 + qix * d0 + qiy * d3 - qiz * d2v;
        float u2 = qiw * d2v - qix * d3 + qiy * d0 + qiz * d1;
        float u3 = qiw * d3 + qix * d2v - qiy * d1 + qiz * d0;
        if (!mi) { u0 = 1.0f; u1 = 0.0f; u2 = 0.0f; u3 = 0.0f; }
        nrm = fmaxf(sqrtf(u0 * u0 + u1 * u1 + u2 * u2 + u3 * u3), 1e-12f);
        inv = 1.0f / nrm;
        out_q[node * 4 + 0] = u0 * inv;
        out_q[node * 4 + 1] = u1 * inv;
        out_q[node * 4 + 2] = u2 * inv;
        out_q[node * 4 + 3] = u3 * inv;
    }
    if (tid >= 4 && tid < 7) {
        int c = tid - 4;
        out_x[node * 3 + c] = s->xi[c] + s->xacc[c] / s->nn;
    }
    if (tid >= 32 && tid < 39) {
        int p = tid - 32;
        float a = s->traw[p * 2 + 0];
        float c = s->traw[p * 2 + 1];
        float nrm = fmaxf(sqrtf(a * a + c * c), 1e-12f);
        out_t[node * 14 + p * 2 + 0] = a / nrm;
        out_t[node * 14 + p * 2 + 1] = c / nrm;
    }
}

extern "C" void kernel_launch(void* const* d_in, const int* in_sizes, int n_in,
                              void* d_out, int out_size)
{
    const float* q  = (const float*)d_in[0];
    const float* x  = (const float*)d_in[1];
    // d_in[2] = torsions (values unused)
    const float* h  = (const float*)d_in[3];
    const float* e  = (const float*)d_in[4];
    const int* node_mask = (const int*)d_in[5];
    const float* pq = (const float*)d_in[6];
    const float* px = (const float*)d_in[7];
    const float* pe = (const float*)d_in[8];
    const float* ph = (const float*)d_in[9];
    const int* pmask = (const int*)d_in[10];
    const float* Wm1 = (const float*)d_in[11];
    const float* bm1 = (const float*)d_in[12];
    const float* Wm2 = (const float*)d_in[13];
    const float* bm2 = (const float*)d_in[14];
    const float* Wf1 = (const float*)d_in[15];
    const float* bf1 = (const float*)d_in[16];
    const float* Wf2 = (const float*)d_in[17];
    const float* bf2 = (const float*)d_in[18];
    const float* Wx1 = (const float*)d_in[19];
    const float* bx1 = (const float*)d_in[20];
    const float* Wx2 = (const float*)d_in[21];
    const float* bx2 = (const float*)d_in[22];
    const float* Wq1 = (const float*)d_in[23];
    const float* bq1 = (const float*)d_in[24];
    const float* Wq2 = (const float*)d_in[25];
    const float* bq2 = (const float*)d_in[26];
    const float* Wt1 = (const float*)d_in[27];
    const float* bt1 = (const float*)d_in[28];
    const float* Wt2 = (const float*)d_in[29];
    const float* bt2 = (const float*)d_in[30];

    dim3 pgrid(NJt / 64, Bb);
    hjproj_kernel<<<pgrid, 256>>>(h, ph, Wm1);

    const size_t smem = sizeof(Smem);
    cudaFuncSetAttribute(egnn_kernel, cudaFuncAttributeMaxDynamicSharedMemorySize,
                         (int)smem);
    dim3 grid(Nn, Bb);
    egnn_kernel<<<grid, NT, smem>>>(
        q, x, h, e, node_mask, pq, px, pe, ph, pmask,
        Wm1, bm1, Wm2, bm2, Wf1, bf1, Wf2, bf2,
        Wx1, bx1, Wx2, bx2, Wq1, bq1, Wq2, bq2, Wt1, bt1, Wt2, bt2,
        (float*)d_out);
}

// round 12
// speedup vs baseline: 3.1614x; 1.2297x over previous
#include <cuda_runtime.h>
#include <math.h>

#define Bb 4
#define Nn 128
#define Pp 512
#define Ee 32
#define NJt 640         // n + p
#define FfB 44          // Phase-B feat row: 32 e + 9 geom + 3 pad
#define TJ 128          // j-tile rows
#define NTILE 5         // 640 / 128
#define HS 68           // hid row stride (floats, mult of 4)
#define NT 512          // threads per CTA

__device__ float g_hjproj[Bb * NJt * 64];   // h_all[b,j] @ Wm1[64:128]
__device__ float g_W2x[64 * 64];            // Wm2 @ Wx1
__device__ float g_b2x[64];                 // bm2 @ Wx1 + bx1

struct __align__(16) Smem {
    float Wm1[FfB * 64];   // rows 0..40 = Wm1[128..168], rows 41..43 zero
    float W2x[64 * 64];
    float Wx2[64 * 3];
    float bm1h[64];        // bm1 + hi @ Wm1[0:64]
    float b2x[64];
    float bx2[4];
    float feat[TJ * FfB];  // 128 x 44
    float hid[TJ * HS];    // 128 x 68
    float hi[64];
    float maskj[TJ];
    float rotq[TJ * 4];
    float hs_part[32 * 64];   // per-jb-group hidsum partials
    float xpart[TJ * 3];
    float msum_h[64];         // reduced hidsum
    float msum[64];
    float hidf[64];
    float hidt[64];
    float hidq[64];
    float traw[16];
    float dqraw[4];
    float xacc[4];
    float qi[4];
    float xi[4];
    float nn;
};

#define RANK1(CMP_, WV_) \
    acc[0][0] += a0.CMP_ * WV_.x; acc[0][1] += a0.CMP_ * WV_.y; acc[0][2] += a0.CMP_ * WV_.z; acc[0][3] += a0.CMP_ * WV_.w; \
    acc[1][0] += a1.CMP_ * WV_.x; acc[1][1] += a1.CMP_ * WV_.y; acc[1][2] += a1.CMP_ * WV_.z; acc[1][3] += a1.CMP_ * WV_.w; \
    acc[2][0] += a2.CMP_ * WV_.x; acc[2][1] += a2.CMP_ * WV_.y; acc[2][2] += a2.CMP_ * WV_.z; acc[2][3] += a2.CMP_ * WV_.w; \
    acc[3][0] += a3.CMP_ * WV_.x; acc[3][1] += a3.CMP_ * WV_.y; acc[3][2] += a3.CMP_ * WV_.z; acc[3][3] += a3.CMP_ * WV_.w;

template<int KVCOUNT, int SSTRIDE>
__device__ __forceinline__ void gemm16(const float* __restrict__ src,
                                       const float* __restrict__ wcol,
                                       float acc[4][4])
{
    #pragma unroll 2
    for (int kv = 0; kv < KVCOUNT; kv++) {
        float4 a0 = *(const float4*)(src + 0 * SSTRIDE + kv * 4);
        float4 a1 = *(const float4*)(src + 1 * SSTRIDE + kv * 4);
        float4 a2 = *(const float4*)(src + 2 * SSTRIDE + kv * 4);
        float4 a3 = *(const float4*)(src + 3 * SSTRIDE + kv * 4);
        float4 w0 = *(const float4*)(wcol + (kv * 4 + 0) * 64);
        float4 w1 = *(const float4*)(wcol + (kv * 4 + 1) * 64);
        float4 w2 = *(const float4*)(wcol + (kv * 4 + 2) * 64);
        float4 w3 = *(const float4*)(wcol + (kv * 4 + 3) * 64);
        RANK1(x, w0)
        RANK1(y, w1)
        RANK1(z, w2)
        RANK1(w, w3)
    }
}

// ---- prologue 1: hjproj[b,j,:] = h_all[b,j,:] @ Wm1[64:128,:] ----
__global__ void __launch_bounds__(256)
hjproj_kernel(const float* __restrict__ h, const float* __restrict__ ph,
              const float* __restrict__ Wm1)
{
    __shared__ float sh[64 * 64];
    __shared__ float sw[64 * 64];
    const int j0 = blockIdx.x * 64;
    const int b = blockIdx.y;
    const int tid = threadIdx.x;

    {
        const float4* g4 = (const float4*)(Wm1 + 64 * 64);
        float4* s4 = (float4*)sw;
        for (int idx = tid; idx < 1024; idx += 256) s4[idx] = g4[idx];
    }
    for (int idx = tid; idx < 64 * 16; idx += 256) {
        int row = idx >> 4, c = idx & 15;
        int j = j0 + row;
        const float4* hrow = (j < Nn) ? (const float4*)&h[(b * Nn + j) * 64]
                                      : (const float4*)&ph[(b * Pp + (j - Nn)) * 64];
        *(float4*)&sh[row * 64 + c * 4] = hrow[c];
    }
    __syncthreads();

    int row = tid >> 2;
    int cq = tid & 3;
    float acc[16] = {};
    #pragma unroll 4
    for (int k = 0; k < 64; k++) {
        float hv = sh[row * 64 + k];
        const float* wr = &sw[k * 64 + cq * 16];
        #pragma unroll
        for (int c = 0; c < 16; c++) acc[c] += hv * wr[c];
    }
    float4* op = (float4*)&g_hjproj[((size_t)(b * NJt) + j0 + row) * 64 + cq * 16];
    op[0] = make_float4(acc[0], acc[1], acc[2], acc[3]);
    op[1] = make_float4(acc[4], acc[5], acc[6], acc[7]);
    op[2] = make_float4(acc[8], acc[9], acc[10], acc[11]);
    op[3] = make_float4(acc[12], acc[13], acc[14], acc[15]);
}

// ---- prologue 2: W2x = Wm2 @ Wx1 ; b2x = bm2 @ Wx1 + bx1 ----
__global__ void __launch_bounds__(256)
w2x_kernel(const float* __restrict__ Wm2, const float* __restrict__ Wx1,
           const float* __restrict__ bm2, const float* __restrict__ bx1)
{
    __shared__ float sA[64 * 64];
    __shared__ float sB[64 * 64];
    const int tid = threadIdx.x;
    {
        const float4* g4 = (const float4*)Wm2;
        float4* s4 = (float4*)sA;
        for (int idx = tid; idx < 1024; idx += 256) s4[idx] = g4[idx];
        g4 = (const float4*)Wx1; s4 = (float4*)sB;
        for (int idx = tid; idx < 1024; idx += 256) s4[idx] = g4[idx];
    }
    __syncthreads();

    int row = tid >> 2;
    int cq = tid & 3;
    float acc[16] = {};
    #pragma unroll 4
    for (int k = 0; k < 64; k++) {
        float a = sA[row * 64 + k];
        const float* wr = &sB[k * 64 + cq * 16];
        #pragma unroll
        for (int c = 0; c < 16; c++) acc[c] += a * wr[c];
    }
    float4* op = (float4*)&g_W2x[row * 64 + cq * 16];
    op[0] = make_float4(acc[0], acc[1], acc[2], acc[3]);
    op[1] = make_float4(acc[4], acc[5], acc[6], acc[7]);
    op[2] = make_float4(acc[8], acc[9], acc[10], acc[11]);
    op[3] = make_float4(acc[12], acc[13], acc[14], acc[15]);

    if (tid < 64) {
        float bv = bx1[tid];
        #pragma unroll 4
        for (int k = 0; k < 64; k++) bv += bm2[k] * sB[k * 64 + tid];
        g_b2x[tid] = bv;
    }
}

__global__ void __launch_bounds__(NT, 1)
egnn_kernel(const float* __restrict__ q, const float* __restrict__ x,
            const float* __restrict__ h, const float* __restrict__ e,
            const int* __restrict__ node_mask,
            const float* __restrict__ pq, const float* __restrict__ px,
            const float* __restrict__ pe, const float* __restrict__ ph,
            const int* __restrict__ pmask,
            const float* __restrict__ Wm1, const float* __restrict__ bm1,
            const float* __restrict__ Wm2, const float* __restrict__ bm2,
            const float* __restrict__ Wf1, const float* __restrict__ bf1,
            const float* __restrict__ Wf2, const float* __restrict__ bf2,
            const float* __restrict__ Wx1, const float* __restrict__ bx1,
            const float* __restrict__ Wx2, const float* __restrict__ bx2,
            const float* __restrict__ Wq1, const float* __restrict__ bq1,
            const float* __restrict__ Wq2, const float* __restrict__ bq2,
            const float* __restrict__ Wt1, const float* __restrict__ bt1,
            const float* __restrict__ Wt2, const float* __restrict__ bt2,
            float* __restrict__ out)
{
    extern __shared__ float smem_raw[];
    Smem* s = (Smem*)smem_raw;
    const int i = blockIdx.x;
    const int b = blockIdx.y;
    const int tid = threadIdx.x;

    // ---- stage weights & node-i data ----
    {
        const float4* g4 = (const float4*)(Wm1 + 128 * 64);
        float4* s4 = (float4*)s->Wm1;
        for (int idx = tid; idx < 41 * 16; idx += NT) s4[idx] = g4[idx];
        for (int idx = tid; idx < 3 * 16; idx += NT)
            s4[41 * 16 + idx] = make_float4(0.f, 0.f, 0.f, 0.f);
        g4 = (const float4*)g_W2x; s4 = (float4*)s->W2x;
        for (int idx = tid; idx < 1024; idx += NT) s4[idx] = g4[idx];
        g4 = (const float4*)Wx2; s4 = (float4*)s->Wx2;
        for (int idx = tid; idx < 48; idx += NT) s4[idx] = g4[idx];
    }
    if (tid < 64) {
        s->b2x[tid] = g_b2x[tid];
        s->hi[tid] = h[(b * Nn + i) * 64 + tid];
    }
    if (tid < 3) s->bx2[tid] = bx2[tid];
    if (tid < 4) s->qi[tid] = q[(b * Nn + i) * 4 + tid];
    if (tid < 3) s->xi[tid] = x[(b * Nn + i) * 3 + tid];
    if (tid == 0) s->nn = -1.0f;
    __syncthreads();

    // n_neigh
    {
        float cnt = 0.0f;
        for (int jj = tid; jj < Nn; jj += NT) cnt += node_mask[b * Nn + jj] ? 1.0f : 0.0f;
        for (int jj = tid; jj < Pp; jj += NT) cnt += pmask[b * Pp + jj] ? 1.0f : 0.0f;
        #pragma unroll
        for (int off = 16; off; off >>= 1) cnt += __shfl_down_sync(0xffffffff, cnt, off);
        if ((tid & 31) == 0) atomicAdd(&s->nn, cnt);
    }
    // hoisted bias: bm1h = bm1 + hi @ Wm1[0:64]
    if (tid < 64) {
        float acc = bm1[tid];
        #pragma unroll 4
        for (int k = 0; k < 64; k++) acc += s->hi[k] * Wm1[k * 64 + tid];
        s->bm1h[tid] = acc;
    }
    __syncthreads();

    const float qiw = s->qi[0], qix = s->qi[1], qiy = s->qi[2], qiz = s->qi[3];
    const float xi0 = s->xi[0], xi1 = s->xi[1], xi2 = s->xi[2];
    const int mi = node_mask[b * Nn + i];

    const int jb = tid >> 4;      // 0..31 -> block of 4 j rows
    const int cb = tid & 15;      // 0..15 -> block of 4 output cols

    float wx2v[4][3];
    #pragma unroll
    for (int c2 = 0; c2 < 4; c2++)
        #pragma unroll
        for (int cc = 0; cc < 3; cc++)
            wx2v[c2][cc] = s->Wx2[(cb * 4 + c2) * 3 + cc];
    const float bx20 = s->bx2[0], bx21 = s->bx2[1], bx22 = s->bx2[2];

    float4 hs = make_float4(0.f, 0.f, 0.f, 0.f);   // Σ mask*hid over this thread's rows/cols
    float xacc0 = 0.0f, xacc1 = 0.0f, xacc2 = 0.0f;

    const float* hjp_base = &g_hjproj[(size_t)b * NJt * 64 + cb * 4];

    for (int tile = 0; tile < NTILE; tile++) {
        const int j0 = tile * TJ;
        __syncthreads();

        // ---------- Phase A: build feature tile (e | geom | pad) ----------
        for (int idx = tid; idx < TJ * 8; idx += NT) {
            int row = idx >> 3, c = idx & 7;
            int j = j0 + row;
            const float4* erow = (j < Nn)
                ? (const float4*)&e[((size_t)(b * Nn + i) * Nn + j) * Ee]
                : (const float4*)&pe[((size_t)(b * Nn + i) * Pp + (j - Nn)) * Ee];
            *(float4*)&s->feat[row * FfB + c * 4] = erow[c];
        }
        if (tid < TJ) {
            int j = j0 + tid;
            float qjw, qjx, qjy, qjz, xj0, xj1, xj2;
            int mj;
            if (j < Nn) {
                const float* qp = &q[(b * Nn + j) * 4];
                qjw = qp[0]; qjx = qp[1]; qjy = qp[2]; qjz = qp[3];
                const float* xp = &x[(b * Nn + j) * 3];
                xj0 = xp[0]; xj1 = xp[1]; xj2 = xp[2];
                mj = (node_mask[b * Nn + j] && (j != i)) ? 1 : 0;
            } else {
                int jp = j - Nn;
                const float* qp = &pq[(b * Pp + jp) * 4];
                qjw = qp[0]; qjx = qp[1]; qjy = qp[2]; qjz = qp[3];
                const float* xp = &px[(b * Pp + jp) * 3];
                xj0 = xp[0]; xj1 = xp[1]; xj2 = xp[2];
                mj = pmask[b * Pp + jp] ? 1 : 0;
            }
            s->maskj[tid] = (mi && mj) ? 1.0f : 0.0f;

            float d0 = xi0 - xj0, d1 = xi1 - xj1, dz = xi2 - xj2;
            float dd = d0 * d0 + d1 * d1 + dz * dz;
            float qd = fabsf(qiw * qjw + qix * qjx + qiy * qjy + qiz * qjz);
            float vx = -qjx, vy = -qjy, vz = -qjz;
            float tx = 2.0f * (vy * dz - vz * d1);
            float ty = 2.0f * (vz * d0 - vx * dz);
            float tz = 2.0f * (vx * d1 - vy * d0);
            float lx0 = d0 + qjw * tx + (vy * tz - vz * ty);
            float lx1 = d1 + qjw * ty + (vz * tx - vx * tz);
            float lx2 = dz + qjw * tz + (vx * ty - vy * tx);
            float lq0 = qjw * qiw - vx * qix - vy * qiy - vz * qiz;
            float lq1 = qjw * qix + vx * qiw + vy * qiz - vz * qiy;
            float lq2 = qjw * qiy - vx * qiz + vy * qiw + vz * qix;
            float lq3 = qjw * qiz + vx * qiy - vy * qix + vz * qiw;
            float* fr = &s->feat[tid * FfB + 32];
            fr[0] = lx0; fr[1] = lx1; fr[2] = lx2;
            fr[3] = lq0; fr[4] = lq1; fr[5] = lq2; fr[6] = lq3;
            fr[7] = dd; fr[8] = qd;
            fr[9] = 0.0f; fr[10] = 0.0f; fr[11] = 0.0f;
            float qn = fmaxf(sqrtf(qjw * qjw + qjx * qjx + qjy * qjy + qjz * qjz), 1e-12f);
            float inv = 1.0f / qn;
            s->rotq[tid * 4 + 0] = qjw * inv;
            s->rotq[tid * 4 + 1] = qjx * inv;
            s->rotq[tid * 4 + 2] = qjy * inv;
            s->rotq[tid * 4 + 3] = qjz * inv;
        }
        __syncthreads();

        // ---------- Phase B: hid = relu(featB @ Wm1[128:] + bm1h + hjproj[j]) ;
        //                     hidsum += mask*hid (registers) ----------
        {
            const float* hp = hjp_base + (size_t)(j0 + jb * 4) * 64;
            float4 hp0 = *(const float4*)(hp + 0 * 64);
            float4 hp1 = *(const float4*)(hp + 1 * 64);
            float4 hp2 = *(const float4*)(hp + 2 * 64);
            float4 hp3 = *(const float4*)(hp + 3 * 64);

            float acc[4][4] = {};
            gemm16<FfB / 4, FfB>(&s->feat[(jb * 4) * FfB], &s->Wm1[cb * 4], acc);
            float4 bb = *(const float4*)&s->bm1h[cb * 4];
            float* hr = &s->hid[(jb * 4) * HS + cb * 4];
            float4 hpv[4] = {hp0, hp1, hp2, hp3};
            #pragma unroll
            for (int r = 0; r < 4; r++) {
                float mk = s->maskj[jb * 4 + r];
                float4 o;
                o.x = fmaxf(acc[r][0] + bb.x + hpv[r].x, 0.0f);
                o.y = fmaxf(acc[r][1] + bb.y + hpv[r].y, 0.0f);
                o.z = fmaxf(acc[r][2] + bb.z + hpv[r].z, 0.0f);
                o.w = fmaxf(acc[r][3] + bb.w + hpv[r].w, 0.0f);
                *(float4*)(hr + r * HS) = o;
                hs.x += mk * o.x; hs.y += mk * o.y;
                hs.z += mk * o.z; hs.w += mk * o.w;
            }
        }
        __syncwarp();   // writers == readers: same 16-thread group

        // ---------- Phase D: hid2 = relu(hid @ W2x + b2x) -> registers ----------
        float d2[4][4];
        {
            float acc[4][4] = {};
            gemm16<16, HS>(&s->hid[(jb * 4) * HS], &s->W2x[cb * 4], acc);
            float4 bb = *(const float4*)&s->b2x[cb * 4];
            #pragma unroll
            for (int r = 0; r < 4; r++) {
                d2[r][0] = fmaxf(acc[r][0] + bb.x, 0.0f);
                d2[r][1] = fmaxf(acc[r][1] + bb.y, 0.0f);
                d2[r][2] = fmaxf(acc[r][2] + bb.z, 0.0f);
                d2[r][3] = fmaxf(acc[r][3] + bb.w, 0.0f);
            }
        }

        // ---------- Phase E: dx partials -> 16-lane bfly reduce -> rotate ----------
        {
            float p[4][3];
            #pragma unroll
            for (int r = 0; r < 4; r++) {
                #pragma unroll
                for (int cc = 0; cc < 3; cc++) {
                    p[r][cc] = d2[r][0] * wx2v[0][cc] + d2[r][1] * wx2v[1][cc]
                             + d2[r][2] * wx2v[2][cc] + d2[r][3] * wx2v[3][cc];
                }
            }
            #pragma unroll
            for (int mskp = 1; mskp < 16; mskp <<= 1) {
                #pragma unroll
                for (int r = 0; r < 4; r++) {
                    #pragma unroll
                    for (int cc = 0; cc < 3; cc++)
                        p[r][cc] += __shfl_xor_sync(0xffffffffu, p[r][cc], mskp);
                }
            }
            if (cb < 4) {
                float a0, a1, a2;
                if      (cb == 0) { a0 = p[0][0]; a1 = p[0][1]; a2 = p[0][2]; }
                else if (cb == 1) { a0 = p[1][0]; a1 = p[1][1]; a2 = p[1][2]; }
                else if (cb == 2) { a0 = p[2][0]; a1 = p[2][1]; a2 = p[2][2]; }
                else              { a0 = p[3][0]; a1 = p[3][1]; a2 = p[3][2]; }
                int row = jb * 4 + cb;
                float mk = s->maskj[row];
                a0 = (a0 + bx20) * mk;
                a1 = (a1 + bx21) * mk;
                a2 = (a2 + bx22) * mk;
                float w  = s->rotq[row * 4 + 0];
                float vx = s->rotq[row * 4 + 1];
                float vy = s->rotq[row * 4 + 2];
                float vz = s->rotq[row * 4 + 3];
                float tx = 2.0f * (vy * a2 - vz * a1);
                float ty = 2.0f * (vz * a0 - vx * a2);
                float tz = 2.0f * (vx * a1 - vy * a0);
                xacc0 += a0 + w * tx + (vy * tz - vz * ty);
                xacc1 += a1 + w * ty + (vz * tx - vx * tz);
                xacc2 += a2 + w * tz + (vx * ty - vy * tx);
            }
        }
    }

    // ---- write per-thread partials, reduce ----
    __syncthreads();
    {
        float* mp = &s->hs_part[jb * 64 + cb * 4];
        mp[0] = hs.x; mp[1] = hs.y; mp[2] = hs.z; mp[3] = hs.w;
    }
    if (cb < 4) {
        int row = jb * 4 + cb;
        s->xpart[row * 3 + 0] = xacc0;
        s->xpart[row * 3 + 1] = xacc1;
        s->xpart[row * 3 + 2] = xacc2;
    }
    __syncthreads();
    if (tid < 64) {
        float acc = 0.0f;
        #pragma unroll 4
        for (int g = 0; g < 32; g++) acc += s->hs_part[g * 64 + tid];
        s->msum_h[tid] = acc;      // hidsum[k], k = tid
    }
    __syncthreads();
    // msum = hidsum @ Wm2 + (mi ? nn : 0) * bm2
    if (tid < 64) {
        float acc = (mi ? s->nn : 0.0f) * bm2[tid];
        #pragma unroll 4
        for (int k = 0; k < 64; k++) acc += s->msum_h[k] * Wm2[k * 64 + tid];
        s->msum[tid] = acc;
    }
    __syncthreads();

    const int grp = tid >> 6, lt = tid & 63;
    if (grp == 0) {
        float acc = bf1[lt];
        #pragma unroll 4
        for (int k = 0; k < 64; k++) acc += s->hi[k] * Wf1[k * 64 + lt];
        #pragma unroll 4
        for (int k = 0; k < 64; k++) acc += s->msum[k] * Wf1[(64 + k) * 64 + lt];
        s->hidf[lt] = fmaxf(acc, 0.0f);
    } else if (grp == 1) {
        float acc = bt1[lt];
        #pragma unroll 4
        for (int k = 0; k < 64; k++) acc += s->msum[k] * Wt1[k * 64 + lt];
        s->hidt[lt] = fmaxf(acc, 0.0f);
    } else if (grp == 2) {
        float acc = bq1[lt];
        #pragma unroll 4
        for (int k = 0; k < 64; k++) acc += s->msum[k] * Wq1[k * 64 + lt];
        s->hidq[lt] = fmaxf(acc, 0.0f);
    } else if (grp == 3 && lt < 3) {
        float sum = 0.0f;
        #pragma unroll 4
        for (int j = 0; j < TJ; j++) sum += s->xpart[j * 3 + lt];
        s->xacc[lt] = sum;
    }
    __syncthreads();

    float* out_q = out;
    float* out_x = out + Bb * Nn * 4;
    float* out_t = out + Bb * Nn * 7;
    float* out_o = out + Bb * Nn * 21;
    const int node = b * Nn + i;

    if (grp == 0) {
        float acc = bf2[lt];
        #pragma unroll 4
        for (int u = 0; u < 64; u++) acc += s->hidf[u] * Wf2[u * 64 + lt];
        out_o[node * 64 + lt] = acc;
    } else if (grp == 1 && lt < 14) {
        float acc = bt2[lt];
        #pragma unroll 4
        for (int u = 0; u < 64; u++) acc += s->hidt[u] * Wt2[u * 14 + lt];
        s->traw[lt] = acc;
    } else if (grp == 2 && lt < 4) {
        float acc = bq2[lt];
        #pragma unroll 4
        for (int u = 0; u < 64; u++) acc += s->hidq[u] * Wq2[u * 4 + lt];
        s->dqraw[lt] = acc;
    }
    __syncthreads();

    if (tid == 0) {
        float d0 = s->dqraw[0], d1 = s->dqraw[1], d2v = s->dqraw[2], d3 = s->dqraw[3];
        if (!mi) { d0 = 1.0f; d1 = 0.0f; d2v = 0.0f; d3 = 0.0f; }
        float nrm = fmaxf(sqrtf(d0 * d0 + d1 * d1 + d2v * d2v + d3 * d3), 1e-12f);
        float inv = 1.0f / nrm;
        d0 *= inv; d1 *= inv; d2v *= inv; d3 *= inv;
        float u0 = qiw * d0 - qix * d1 - qiy * d2v - qiz * d3;
        float u1 = qiw * d1 + qix * d0 + qiy * d3 - qiz * d2v;
        float u2 = qiw * d2v - qix * d3 + qiy * d0 + qiz * d1;
        float u3 = qiw * d3 + qix * d2v - qiy * d1 + qiz * d0;
        if (!mi) { u0 = 1.0f; u1 = 0.0f; u2 = 0.0f; u3 = 0.0f; }
        nrm = fmaxf(sqrtf(u0 * u0 + u1 * u1 + u2 * u2 + u3 * u3), 1e-12f);
        inv = 1.0f / nrm;
        out_q[node * 4 + 0] = u0 * inv;
        out_q[node * 4 + 1] = u1 * inv;
        out_q[node * 4 + 2] = u2 * inv;
        out_q[node * 4 + 3] = u3 * inv;
    }
    if (tid >= 4 && tid < 7) {
        int c = tid - 4;
        out_x[node * 3 + c] = s->xi[c] + s->xacc[c] / s->nn;
    }
    if (tid >= 32 && tid < 39) {
        int p = tid - 32;
        float a = s->traw[p * 2 + 0];
        float c = s->traw[p * 2 + 1];
        float nrm = fmaxf(sqrtf(a * a + c * c), 1e-12f);
        out_t[node * 14 + p * 2 + 0] = a / nrm;
        out_t[node * 14 + p * 2 + 1] = c / nrm;
    }
}

extern "C" void kernel_launch(void* const* d_in, const int* in_sizes, int n_in,
                              void* d_out, int out_size)
{
    const float* q  = (const float*)d_in[0];
    const float* x  = (const float*)d_in[1];
    // d_in[2] = torsions (values unused)
    const float* h  = (const float*)d_in[3];
    const float* e  = (const float*)d_in[4];
    const int* node_mask = (const int*)d_in[5];
    const float* pq = (const float*)d_in[6];
    const float* px = (const float*)d_in[7];
    const float* pe = (const float*)d_in[8];
    const float* ph = (const float*)d_in[9];
    const int* pmask = (const int*)d_in[10];
    const float* Wm1 = (const float*)d_in[11];
    const float* bm1 = (const float*)d_in[12];
    const float* Wm2 = (const float*)d_in[13];
    const float* bm2 = (const float*)d_in[14];
    const float* Wf1 = (const float*)d_in[15];
    const float* bf1 = (const float*)d_in[16];
    const float* Wf2 = (const float*)d_in[17];
    const float* bf2 = (const float*)d_in[18];
    const float* Wx1 = (const float*)d_in[19];
    const float* bx1 = (const float*)d_in[20];
    const float* Wx2 = (const float*)d_in[21];
    const float* bx2 = (const float*)d_in[22];
    const float* Wq1 = (const float*)d_in[23];
    const float* bq1 = (const float*)d_in[24];
    const float* Wq2 = (const float*)d_in[25];
    const float* bq2 = (const float*)d_in[26];
    const float* Wt1 = (const float*)d_in[27];
    const float* bt1 = (const float*)d_in[28];
    const float* Wt2 = (const float*)d_in[29];
    const float* bt2 = (const float*)d_in[30];

    dim3 pgrid(NJt / 64, Bb);
    hjproj_kernel<<<pgrid, 256>>>(h, ph, Wm1);
    w2x_kernel<<<1, 256>>>(Wm2, Wx1, bm2, bx1);

    const size_t smem = sizeof(Smem);
    cudaFuncSetAttribute(egnn_kernel, cudaFuncAttributeMaxDynamicSharedMemorySize,
                         (int)smem);
    dim3 grid(Nn, Bb);
    egnn_kernel<<<grid, NT, smem>>>(
        q, x, h, e, node_mask, pq, px, pe, ph, pmask,
        Wm1, bm1, Wm2, bm2, Wf1, bf1, Wf2, bf2,
        Wx1, bx1, Wx2, bx2, Wq1, bq1, Wq2, bq2, Wt1, bt1, Wt2, bt2,
        (float*)d_out);
}

// round 13
// speedup vs baseline: 3.7344x; 1.1812x over previous
#include <cuda_runtime.h>
#include <math.h>

#define Bb 4
#define Nn 128
#define Pp 512
#define Ee 32
#define NJt 640         // n + p
#define FfB 44          // Phase-B feat row: 32 e + 9 geom + 3 pad
#define TJ 128          // j-tile rows per CTA
#define NTILE 5         // 640 / 128 tiles (one per CTA in z)
#define HS 68           // hid row stride (floats, mult of 4)
#define NT 512          // threads per main CTA

__device__ float g_hjproj[Bb * NJt * 64];        // h_all[b,j] @ Wm1[64:128]
__device__ float g_W2x[64 * 64];                 // Wm2 @ Wx1
__device__ float g_b2x[64];                      // bm2 @ Wx1 + bx1
__device__ float g_hs_part[Bb * Nn * NTILE * 64];  // per-tile hidsum partials
__device__ float g_x_part[Bb * Nn * NTILE * 4];    // per-tile xacc partials

struct __align__(16) Smem {
    float Wm1[FfB * 64];
    float W2x[64 * 64];
    float Wx2[64 * 3];
    float bm1h[64];
    float b2x[64];
    float bx2[4];
    float feat[TJ * FfB];
    float hid[TJ * HS];
    float hi[64];
    float maskj[TJ];
    float rotq[TJ * 4];
    float hs_part[32 * 64];
    float xpart[TJ * 3];
    float qi[4];
    float xi[4];
};

#define RANK1(CMP_, WV_) \
    acc[0][0] += a0.CMP_ * WV_.x; acc[0][1] += a0.CMP_ * WV_.y; acc[0][2] += a0.CMP_ * WV_.z; acc[0][3] += a0.CMP_ * WV_.w; \
    acc[1][0] += a1.CMP_ * WV_.x; acc[1][1] += a1.CMP_ * WV_.y; acc[1][2] += a1.CMP_ * WV_.z; acc[1][3] += a1.CMP_ * WV_.w; \
    acc[2][0] += a2.CMP_ * WV_.x; acc[2][1] += a2.CMP_ * WV_.y; acc[2][2] += a2.CMP_ * WV_.z; acc[2][3] += a2.CMP_ * WV_.w; \
    acc[3][0] += a3.CMP_ * WV_.x; acc[3][1] += a3.CMP_ * WV_.y; acc[3][2] += a3.CMP_ * WV_.z; acc[3][3] += a3.CMP_ * WV_.w;

template<int KVCOUNT, int SSTRIDE>
__device__ __forceinline__ void gemm16(const float* __restrict__ src,
                                       const float* __restrict__ wcol,
                                       float acc[4][4])
{
    #pragma unroll 2
    for (int kv = 0; kv < KVCOUNT; kv++) {
        float4 a0 = *(const float4*)(src + 0 * SSTRIDE + kv * 4);
        float4 a1 = *(const float4*)(src + 1 * SSTRIDE + kv * 4);
        float4 a2 = *(const float4*)(src + 2 * SSTRIDE + kv * 4);
        float4 a3 = *(const float4*)(src + 3 * SSTRIDE + kv * 4);
        float4 w0 = *(const float4*)(wcol + (kv * 4 + 0) * 64);
        float4 w1 = *(const float4*)(wcol + (kv * 4 + 1) * 64);
        float4 w2 = *(const float4*)(wcol + (kv * 4 + 2) * 64);
        float4 w3 = *(const float4*)(wcol + (kv * 4 + 3) * 64);
        RANK1(x, w0)
        RANK1(y, w1)
        RANK1(z, w2)
        RANK1(w, w3)
    }
}

// ---- fused prologue ----
// blockIdx.x < 20 : hjproj for 32 j-rows (x*32 .. x*32+31), batch blockIdx.y
// blockIdx.x == 20 && blockIdx.y == 0 : W2x = Wm2 @ Wx1 ; b2x
__global__ void __launch_bounds__(256)
prologue_kernel(const float* __restrict__ h, const float* __restrict__ ph,
                const float* __restrict__ Wm1,
                const float* __restrict__ Wm2, const float* __restrict__ Wx1,
                const float* __restrict__ bm2, const float* __restrict__ bx1)
{
    __shared__ float sw[64 * 64];
    __shared__ float sh[32 * 64];
    const int tid = threadIdx.x;

    if (blockIdx.x < 20) {
        const int j0 = blockIdx.x * 32;
        const int b = blockIdx.y;
        {
            const float4* g4 = (const float4*)(Wm1 + 64 * 64);
            float4* s4 = (float4*)sw;
            for (int idx = tid; idx < 1024; idx += 256) s4[idx] = g4[idx];
        }
        for (int idx = tid; idx < 32 * 16; idx += 256) {
            int row = idx >> 4, c = idx & 15;
            int j = j0 + row;
            const float4* hrow = (j < Nn) ? (const float4*)&h[(b * Nn + j) * 64]
                                          : (const float4*)&ph[(b * Pp + (j - Nn)) * 64];
            *(float4*)&sh[row * 64 + c * 4] = hrow[c];
        }
        __syncthreads();

        int row = tid >> 3;       // 0..31
        int c8 = tid & 7;         // 8 cols each
        float acc[8] = {};
        #pragma unroll 4
        for (int k = 0; k < 64; k++) {
            float hv = sh[row * 64 + k];
            const float* wr = &sw[k * 64 + c8 * 8];
            #pragma unroll
            for (int c = 0; c < 8; c++) acc[c] += hv * wr[c];
        }
        float4* op = (float4*)&g_hjproj[((size_t)(b * NJt) + j0 + row) * 64 + c8 * 8];
        op[0] = make_float4(acc[0], acc[1], acc[2], acc[3]);
        op[1] = make_float4(acc[4], acc[5], acc[6], acc[7]);
    } else if (blockIdx.y == 0) {
        // W2x = Wm2 @ Wx1
        __shared__ float sA[64 * 64];
        {
            const float4* g4 = (const float4*)Wx1;
            float4* s4 = (float4*)sw;
            for (int idx = tid; idx < 1024; idx += 256) s4[idx] = g4[idx];
            g4 = (const float4*)Wm2; s4 = (float4*)sA;
            for (int idx = tid; idx < 1024; idx += 256) s4[idx] = g4[idx];
        }
        __syncthreads();
        int row = tid >> 2;
        int cq = tid & 3;
        float acc[16] = {};
        #pragma unroll 4
        for (int k = 0; k < 64; k++) {
            float a = sA[row * 64 + k];
            const float* wr = &sw[k * 64 + cq * 16];
            #pragma unroll
            for (int c = 0; c < 16; c++) acc[c] += a * wr[c];
        }
        float4* op = (float4*)&g_W2x[row * 64 + cq * 16];
        op[0] = make_float4(acc[0], acc[1], acc[2], acc[3]);
        op[1] = make_float4(acc[4], acc[5], acc[6], acc[7]);
        op[2] = make_float4(acc[8], acc[9], acc[10], acc[11]);
        op[3] = make_float4(acc[12], acc[13], acc[14], acc[15]);
        if (tid < 64) {
            float bv = bx1[tid];
            #pragma unroll 4
            for (int k = 0; k < 64; k++) bv += bm2[k] * sw[k * 64 + tid];
            g_b2x[tid] = bv;
        }
    }
}

// ---- main: one CTA per (i, b, tile) ----
__global__ void __launch_bounds__(NT, 1)
egnn_kernel(const float* __restrict__ q, const float* __restrict__ x,
            const float* __restrict__ h, const float* __restrict__ e,
            const int* __restrict__ node_mask,
            const float* __restrict__ pq, const float* __restrict__ px,
            const float* __restrict__ pe, const float* __restrict__ ph,
            const int* __restrict__ pmask,
            const float* __restrict__ Wm1, const float* __restrict__ bm1,
            const float* __restrict__ Wx2, const float* __restrict__ bx2)
{
    extern __shared__ float smem_raw[];
    Smem* s = (Smem*)smem_raw;
    const int i = blockIdx.x;
    const int b = blockIdx.y;
    const int tile = blockIdx.z;
    const int j0 = tile * TJ;
    const int tid = threadIdx.x;

    // ---- stage weights & node-i data ----
    {
        const float4* g4 = (const float4*)(Wm1 + 128 * 64);
        float4* s4 = (float4*)s->Wm1;
        for (int idx = tid; idx < 41 * 16; idx += NT) s4[idx] = g4[idx];
        for (int idx = tid; idx < 3 * 16; idx += NT)
            s4[41 * 16 + idx] = make_float4(0.f, 0.f, 0.f, 0.f);
        g4 = (const float4*)g_W2x; s4 = (float4*)s->W2x;
        for (int idx = tid; idx < 1024; idx += NT) s4[idx] = g4[idx];
        g4 = (const float4*)Wx2; s4 = (float4*)s->Wx2;
        for (int idx = tid; idx < 48; idx += NT) s4[idx] = g4[idx];
    }
    if (tid < 64) {
        s->b2x[tid] = g_b2x[tid];
        s->hi[tid] = h[(b * Nn + i) * 64 + tid];
    }
    if (tid < 3) s->bx2[tid] = bx2[tid];
    if (tid < 4) s->qi[tid] = q[(b * Nn + i) * 4 + tid];
    if (tid < 3) s->xi[tid] = x[(b * Nn + i) * 3 + tid];
    __syncthreads();

    // hoisted bias: bm1h = bm1 + hi @ Wm1[0:64]
    if (tid < 64) {
        float acc = bm1[tid];
        #pragma unroll 4
        for (int k = 0; k < 64; k++) acc += s->hi[k] * Wm1[k * 64 + tid];
        s->bm1h[tid] = acc;
    }

    const float qiw = s->qi[0], qix = s->qi[1], qiy = s->qi[2], qiz = s->qi[3];
    const float xi0 = s->xi[0], xi1 = s->xi[1], xi2 = s->xi[2];
    const int mi = node_mask[b * Nn + i];

    const int jb = tid >> 4;
    const int cb = tid & 15;

    float wx2v[4][3];
    #pragma unroll
    for (int c2 = 0; c2 < 4; c2++)
        #pragma unroll
        for (int cc = 0; cc < 3; cc++)
            wx2v[c2][cc] = s->Wx2[(cb * 4 + c2) * 3 + cc];
    const float bx20 = s->bx2[0], bx21 = s->bx2[1], bx22 = s->bx2[2];

    const float* hjp_base = &g_hjproj[(size_t)b * NJt * 64 + cb * 4];

    // ---------- Phase A: build feature tile ----------
    for (int idx = tid; idx < TJ * 8; idx += NT) {
        int row = idx >> 3, c = idx & 7;
        int j = j0 + row;
        const float4* erow = (j < Nn)
            ? (const float4*)&e[((size_t)(b * Nn + i) * Nn + j) * Ee]
            : (const float4*)&pe[((size_t)(b * Nn + i) * Pp + (j - Nn)) * Ee];
        *(float4*)&s->feat[row * FfB + c * 4] = erow[c];
    }
    if (tid < TJ) {
        int j = j0 + tid;
        float qjw, qjx, qjy, qjz, xj0, xj1, xj2;
        int mj;
        if (j < Nn) {
            const float* qp = &q[(b * Nn + j) * 4];
            qjw = qp[0]; qjx = qp[1]; qjy = qp[2]; qjz = qp[3];
            const float* xp = &x[(b * Nn + j) * 3];
            xj0 = xp[0]; xj1 = xp[1]; xj2 = xp[2];
            mj = (node_mask[b * Nn + j] && (j != i)) ? 1 : 0;
        } else {
            int jp = j - Nn;
            const float* qp = &pq[(b * Pp + jp) * 4];
            qjw = qp[0]; qjx = qp[1]; qjy = qp[2]; qjz = qp[3];
            const float* xp = &px[(b * Pp + jp) * 3];
            xj0 = xp[0]; xj1 = xp[1]; xj2 = xp[2];
            mj = pmask[b * Pp + jp] ? 1 : 0;
        }
        s->maskj[tid] = (mi && mj) ? 1.0f : 0.0f;

        float d0 = xi0 - xj0, d1 = xi1 - xj1, dz = xi2 - xj2;
        float dd = d0 * d0 + d1 * d1 + dz * dz;
        float qd = fabsf(qiw * qjw + qix * qjx + qiy * qjy + qiz * qjz);
        float vx = -qjx, vy = -qjy, vz = -qjz;
        float tx = 2.0f * (vy * dz - vz * d1);
        float ty = 2.0f * (vz * d0 - vx * dz);
        float tz = 2.0f * (vx * d1 - vy * d0);
        float lx0 = d0 + qjw * tx + (vy * tz - vz * ty);
        float lx1 = d1 + qjw * ty + (vz * tx - vx * tz);
        float lx2 = dz + qjw * tz + (vx * ty - vy * tx);
        float lq0 = qjw * qiw - vx * qix - vy * qiy - vz * qiz;
        float lq1 = qjw * qix + vx * qiw + vy * qiz - vz * qiy;
        float lq2 = qjw * qiy - vx * qiz + vy * qiw + vz * qix;
        float lq3 = qjw * qiz + vx * qiy - vy * qix + vz * qiw;
        float* fr = &s->feat[tid * FfB + 32];
        fr[0] = lx0; fr[1] = lx1; fr[2] = lx2;
        fr[3] = lq0; fr[4] = lq1; fr[5] = lq2; fr[6] = lq3;
        fr[7] = dd; fr[8] = qd;
        fr[9] = 0.0f; fr[10] = 0.0f; fr[11] = 0.0f;
        float qn = fmaxf(sqrtf(qjw * qjw + qjx * qjx + qjy * qjy + qjz * qjz), 1e-12f);
        float inv = 1.0f / qn;
        s->rotq[tid * 4 + 0] = qjw * inv;
        s->rotq[tid * 4 + 1] = qjx * inv;
        s->rotq[tid * 4 + 2] = qjy * inv;
        s->rotq[tid * 4 + 3] = qjz * inv;
    }
    __syncthreads();

    float4 hs = make_float4(0.f, 0.f, 0.f, 0.f);
    float xacc0 = 0.0f, xacc1 = 0.0f, xacc2 = 0.0f;

    // ---------- Phase B: hid = relu(featB @ Wm1[128:] + bm1h + hjproj[j]) ----------
    {
        const float* hp = hjp_base + (size_t)(j0 + jb * 4) * 64;
        float4 hp0 = *(const float4*)(hp + 0 * 64);
        float4 hp1 = *(const float4*)(hp + 1 * 64);
        float4 hp2 = *(const float4*)(hp + 2 * 64);
        float4 hp3 = *(const float4*)(hp + 3 * 64);

        float acc[4][4] = {};
        gemm16<FfB / 4, FfB>(&s->feat[(jb * 4) * FfB], &s->Wm1[cb * 4], acc);
        float4 bb = *(const float4*)&s->bm1h[cb * 4];
        float* hr = &s->hid[(jb * 4) * HS + cb * 4];
        float4 hpv[4] = {hp0, hp1, hp2, hp3};
        #pragma unroll
        for (int r = 0; r < 4; r++) {
            float mk = s->maskj[jb * 4 + r];
            float4 o;
            o.x = fmaxf(acc[r][0] + bb.x + hpv[r].x, 0.0f);
            o.y = fmaxf(acc[r][1] + bb.y + hpv[r].y, 0.0f);
            o.z = fmaxf(acc[r][2] + bb.z + hpv[r].z, 0.0f);
            o.w = fmaxf(acc[r][3] + bb.w + hpv[r].w, 0.0f);
            *(float4*)(hr + r * HS) = o;
            hs.x += mk * o.x; hs.y += mk * o.y;
            hs.z += mk * o.z; hs.w += mk * o.w;
        }
    }
    __syncwarp();

    // ---------- Phase D: hid2 = relu(hid @ W2x + b2x) ----------
    float d2[4][4];
    {
        float acc[4][4] = {};
        gemm16<16, HS>(&s->hid[(jb * 4) * HS], &s->W2x[cb * 4], acc);
        float4 bb = *(const float4*)&s->b2x[cb * 4];
        #pragma unroll
        for (int r = 0; r < 4; r++) {
            d2[r][0] = fmaxf(acc[r][0] + bb.x, 0.0f);
            d2[r][1] = fmaxf(acc[r][1] + bb.y, 0.0f);
            d2[r][2] = fmaxf(acc[r][2] + bb.z, 0.0f);
            d2[r][3] = fmaxf(acc[r][3] + bb.w, 0.0f);
        }
    }

    // ---------- Phase E: dx -> 16-lane bfly reduce -> rotate ----------
    {
        float p[4][3];
        #pragma unroll
        for (int r = 0; r < 4; r++) {
            #pragma unroll
            for (int cc = 0; cc < 3; cc++) {
                p[r][cc] = d2[r][0] * wx2v[0][cc] + d2[r][1] * wx2v[1][cc]
                         + d2[r][2] * wx2v[2][cc] + d2[r][3] * wx2v[3][cc];
            }
        }
        #pragma unroll
        for (int mskp = 1; mskp < 16; mskp <<= 1) {
            #pragma unroll
            for (int r = 0; r < 4; r++) {
                #pragma unroll
                for (int cc = 0; cc < 3; cc++)
                    p[r][cc] += __shfl_xor_sync(0xffffffffu, p[r][cc], mskp);
            }
        }
        if (cb < 4) {
            float a0, a1, a2;
            if      (cb == 0) { a0 = p[0][0]; a1 = p[0][1]; a2 = p[0][2]; }
            else if (cb == 1) { a0 = p[1][0]; a1 = p[1][1]; a2 = p[1][2]; }
            else if (cb == 2) { a0 = p[2][0]; a1 = p[2][1]; a2 = p[2][2]; }
            else              { a0 = p[3][0]; a1 = p[3][1]; a2 = p[3][2]; }
            int row = jb * 4 + cb;
            float mk = s->maskj[row];
            a0 = (a0 + bx20) * mk;
            a1 = (a1 + bx21) * mk;
            a2 = (a2 + bx22) * mk;
            float w  = s->rotq[row * 4 + 0];
            float vx = s->rotq[row * 4 + 1];
            float vy = s->rotq[row * 4 + 2];
            float vz = s->rotq[row * 4 + 3];
            float tx = 2.0f * (vy * a2 - vz * a1);
            float ty = 2.0f * (vz * a0 - vx * a2);
            float tz = 2.0f * (vx * a1 - vy * a0);
            xacc0 = a0 + w * tx + (vy * tz - vz * ty);
            xacc1 = a1 + w * ty + (vz * tx - vx * tz);
            xacc2 = a2 + w * tz + (vx * ty - vy * tx);
        }
    }

    // ---- reduce partials, write to global scratch ----
    __syncthreads();
    {
        float* mp = &s->hs_part[jb * 64 + cb * 4];
        mp[0] = hs.x; mp[1] = hs.y; mp[2] = hs.z; mp[3] = hs.w;
    }
    if (cb < 4) {
        int row = jb * 4 + cb;
        s->xpart[row * 3 + 0] = xacc0;
        s->xpart[row * 3 + 1] = xacc1;
        s->xpart[row * 3 + 2] = xacc2;
    }
    __syncthreads();
    const size_t slot = (size_t)((b * Nn + i) * NTILE + tile);
    if (tid < 64) {
        float acc = 0.0f;
        #pragma unroll 4
        for (int g = 0; g < 32; g++) acc += s->hs_part[g * 64 + tid];
        g_hs_part[slot * 64 + tid] = acc;
    }
    if (tid >= 64 && tid < 67) {
        int c = tid - 64;
        float sum = 0.0f;
        #pragma unroll 4
        for (int j = 0; j < TJ; j++) sum += s->xpart[j * 3 + c];
        g_x_part[slot * 4 + c] = sum;
    }
}

// ---- finalize: one block per node ----
__global__ void __launch_bounds__(256)
finalize_kernel(const float* __restrict__ q, const float* __restrict__ x,
                const float* __restrict__ h,
                const int* __restrict__ node_mask, const int* __restrict__ pmask,
                const float* __restrict__ Wm2, const float* __restrict__ bm2,
                const float* __restrict__ Wf1, const float* __restrict__ bf1,
                const float* __restrict__ Wf2, const float* __restrict__ bf2,
                const float* __restrict__ Wq1, const float* __restrict__ bq1,
                const float* __restrict__ Wq2, const float* __restrict__ bq2,
                const float* __restrict__ Wt1, const float* __restrict__ bt1,
                const float* __restrict__ Wt2, const float* __restrict__ bt2,
                float* __restrict__ out)
{
    __shared__ float msum_h[64];
    __shared__ float msum[64];
    __shared__ float hi[64];
    __shared__ float hidf[64];
    __shared__ float hidt[64];
    __shared__ float hidq[64];
    __shared__ float traw[16];
    __shared__ float dqraw[4];
    __shared__ float xacc[4];
    __shared__ float s_nn;

    const int i = blockIdx.x;
    const int b = blockIdx.y;
    const int tid = threadIdx.x;
    const int node = b * Nn + i;
    const size_t base = (size_t)node * NTILE;

    if (tid == 0) s_nn = -1.0f;
    if (tid < 64) {
        float acc = 0.0f;
        #pragma unroll
        for (int t = 0; t < NTILE; t++) acc += g_hs_part[(base + t) * 64 + tid];
        msum_h[tid] = acc;
        hi[tid] = h[node * 64 + tid];
    }
    if (tid >= 64 && tid < 67) {
        int c = tid - 64;
        float acc = 0.0f;
        #pragma unroll
        for (int t = 0; t < NTILE; t++) acc += g_x_part[(base + t) * 4 + c];
        xacc[c] = acc;
    }
    __syncthreads();

    // n_neigh
    {
        float cnt = 0.0f;
        for (int jj = tid; jj < Nn; jj += 256) cnt += node_mask[b * Nn + jj] ? 1.0f : 0.0f;
        for (int jj = tid; jj < Pp; jj += 256) cnt += pmask[b * Pp + jj] ? 1.0f : 0.0f;
        #pragma unroll
        for (int off = 16; off; off >>= 1) cnt += __shfl_down_sync(0xffffffff, cnt, off);
        if ((tid & 31) == 0) atomicAdd(&s_nn, cnt);
    }
    const int mi = node_mask[node];
    __syncthreads();

    // msum = hidsum @ Wm2 + (mi ? nn : 0) * bm2
    if (tid < 64) {
        float acc = (mi ? s_nn : 0.0f) * bm2[tid];
        #pragma unroll 4
        for (int k = 0; k < 64; k++) acc += msum_h[k] * Wm2[k * 64 + tid];
        msum[tid] = acc;
    }
    __syncthreads();

    const int grp = tid >> 6, lt = tid & 63;
    if (grp == 0) {
        float acc = bf1[lt];
        #pragma unroll 4
        for (int k = 0; k < 64; k++) acc += hi[k] * Wf1[k * 64 + lt];
        #pragma unroll 4
        for (int k = 0; k < 64; k++) acc += msum[k] * Wf1[(64 + k) * 64 + lt];
        hidf[lt] = fmaxf(acc, 0.0f);
    } else if (grp == 1) {
        float acc = bt1[lt];
        #pragma unroll 4
        for (int k = 0; k < 64; k++) acc += msum[k] * Wt1[k * 64 + lt];
        hidt[lt] = fmaxf(acc, 0.0f);
    } else if (grp == 2) {
        float acc = bq1[lt];
        #pragma unroll 4
        for (int k = 0; k < 64; k++) acc += msum[k] * Wq1[k * 64 + lt];
        hidq[lt] = fmaxf(acc, 0.0f);
    }
    __syncthreads();

    float* out_q = out;
    float* out_x = out + Bb * Nn * 4;
    float* out_t = out + Bb * Nn * 7;
    float* out_o = out + Bb * Nn * 21;

    if (grp == 0) {
        float acc = bf2[lt];
        #pragma unroll 4
        for (int u = 0; u < 64; u++) acc += hidf[u] * Wf2[u * 64 + lt];
        out_o[node * 64 + lt] = acc;
    } else if (grp == 1 && lt < 14) {
        float acc = bt2[lt];
        #pragma unroll 4
        for (int u = 0; u < 64; u++) acc += hidt[u] * Wt2[u * 14 + lt];
        traw[lt] = acc;
    } else if (grp == 2 && lt < 4) {
        float acc = bq2[lt];
        #pragma unroll 4
        for (int u = 0; u < 64; u++) acc += hidq[u] * Wq2[u * 4 + lt];
        dqraw[lt] = acc;
    }
    __syncthreads();

    if (tid == 0) {
        float qiw = q[node * 4 + 0], qix = q[node * 4 + 1];
        float qiy = q[node * 4 + 2], qiz = q[node * 4 + 3];
        float d0 = dqraw[0], d1 = dqraw[1], d2v = dqraw[2], d3 = dqraw[3];
        if (!mi) { d0 = 1.0f; d1 = 0.0f; d2v = 0.0f; d3 = 0.0f; }
        float nrm = fmaxf(sqrtf(d0 * d0 + d1 * d1 + d2v * d2v + d3 * d3), 1e-12f);
        float inv = 1.0f / nrm;
        d0 *= inv; d1 *= inv; d2v *= inv; d3 *= inv;
        float u0 = qiw * d0 - qix * d1 - qiy * d2v - qiz * d3;
        float u1 = qiw * d1 + qix * d0 + qiy * d3 - qiz * d2v;
        float u2 = qiw * d2v - qix * d3 + qiy * d0 + qiz * d1;
        float u3 = qiw * d3 + qix * d2v - qiy * d1 + qiz * d0;
        if (!mi) { u0 = 1.0f; u1 = 0.0f; u2 = 0.0f; u3 = 0.0f; }
        nrm = fmaxf(sqrtf(u0 * u0 + u1 * u1 + u2 * u2 + u3 * u3), 1e-12f);
        inv = 1.0f / nrm;
        out_q[node * 4 + 0] = u0 * inv;
        out_q[node * 4 + 1] = u1 * inv;
        out_q[node * 4 + 2] = u2 * inv;
        out_q[node * 4 + 3] = u3 * inv;
    }
    if (tid >= 4 && tid < 7) {
        int c = tid - 4;
        out_x[node * 3 + c] = x[node * 3 + c] + xacc[c] / s_nn;
    }
    if (tid >= 32 && tid < 39) {
        int p = tid - 32;
        float a = traw[p * 2 + 0];
        float c = traw[p * 2 + 1];
        float nrm = fmaxf(sqrtf(a * a + c * c), 1e-12f);
        out_t[node * 14 + p * 2 + 0] = a / nrm;
        out_t[node * 14 + p * 2 + 1] = c / nrm;
    }
}

extern "C" void kernel_launch(void* const* d_in, const int* in_sizes, int n_in,
                              void* d_out, int out_size)
{
    const float* q  = (const float*)d_in[0];
    const float* x  = (const float*)d_in[1];
    // d_in[2] = torsions (values unused)
    const float* h  = (const float*)d_in[3];
    const float* e  = (const float*)d_in[4];
    const int* node_mask = (const int*)d_in[5];
    const float* pq = (const float*)d_in[6];
    const float* px = (const float*)d_in[7];
    const float* pe = (const float*)d_in[8];
    const float* ph = (const float*)d_in[9];
    const int* pmask = (const int*)d_in[10];
    const float* Wm1 = (const float*)d_in[11];
    const float* bm1 = (const float*)d_in[12];
    const float* Wm2 = (const float*)d_in[13];
    const float* bm2 = (const float*)d_in[14];
    const float* Wf1 = (const float*)d_in[15];
    const float* bf1 = (const float*)d_in[16];
    const float* Wf2 = (const float*)d_in[17];
    const float* bf2 = (const float*)d_in[18];
    const float* Wx1 = (const float*)d_in[19];
    const float* bx1 = (const float*)d_in[20];
    const float* Wx2 = (const float*)d_in[21];
    const float* bx2 = (const float*)d_in[22];
    const float* Wq1 = (const float*)d_in[23];
    const float* bq1 = (const float*)d_in[24];
    const float* Wq2 = (const float*)d_in[25];
    const float* bq2 = (const float*)d_in[26];
    const float* Wt1 = (const float*)d_in[27];
    const float* bt1 = (const float*)d_in[28];
    const float* Wt2 = (const float*)d_in[29];
    const float* bt2 = (const float*)d_in[30];

    dim3 pgrid(21, Bb);
    prologue_kernel<<<pgrid, 256>>>(h, ph, Wm1, Wm2, Wx1, bm2, bx1);

    const size_t smem = sizeof(Smem);
    cudaFuncSetAttribute(egnn_kernel, cudaFuncAttributeMaxDynamicSharedMemorySize,
                         (int)smem);
    dim3 grid(Nn, Bb, NTILE);
    egnn_kernel<<<grid, NT, smem>>>(q, x, h, e, node_mask, pq, px, pe, ph, pmask,
                                    Wm1, bm1, Wx2, bx2);

    dim3 fgrid(Nn, Bb);
    finalize_kernel<<<fgrid, 256>>>(q, x, h, node_mask, pmask,
                                    Wm2, bm2, Wf1, bf1, Wf2, bf2,
                                    Wq1, bq1, Wq2, bq2, Wt1, bt1, Wt2, bt2,
                                    (float*)d_out);
}

// round 15
// speedup vs baseline: 3.7717x; 1.0100x over previous
#include <cuda_runtime.h>
#include <math.h>

#define Bb 4
#define Nn 128
#define Pp 512
#define Ee 32
#define NJt 640         // n + p
#define FfB 44          // Phase-B feat row: 32 e + 9 geom + 3 pad
#define TJ 64           // j-tile rows per CTA
#define NTILE 10        // 640 / 64 tiles (one per CTA in z)
#define HS 68           // hid row stride (floats, mult of 4)
#define NT 256          // threads per main CTA

__device__ float g_hjproj[Bb * NJt * 64];          // h_all[b,j] @ Wm1[64:128]
__device__ float g_W2x[64 * 64];                   // Wm2 @ Wx1
__device__ float g_b2x[64];                        // bm2 @ Wx1 + bx1
__device__ float g_hs_part[Bb * Nn * NTILE * 64];  // per-tile hidsum partials
__device__ float g_x_part[Bb * Nn * NTILE * 4];    // per-tile xacc partials

struct __align__(16) Smem {
    float Wm1[FfB * 64];
    float W2x[64 * 64];
    float Wx2[64 * 3];
    float bm1h[64];
    float b2x[64];
    float bx2[4];
    float feat[TJ * FfB];
    float hid[TJ * HS];
    float hi[64];
    float maskj[TJ];
    float rotq[TJ * 4];
    float hs_part[16 * 64];
    float xpart[TJ * 3];
    float qi[4];
    float xi[4];
};

#define RANK1(CMP_, WV_) \
    acc[0][0] += a0.CMP_ * WV_.x; acc[0][1] += a0.CMP_ * WV_.y; acc[0][2] += a0.CMP_ * WV_.z; acc[0][3] += a0.CMP_ * WV_.w; \
    acc[1][0] += a1.CMP_ * WV_.x; acc[1][1] += a1.CMP_ * WV_.y; acc[1][2] += a1.CMP_ * WV_.z; acc[1][3] += a1.CMP_ * WV_.w; \
    acc[2][0] += a2.CMP_ * WV_.x; acc[2][1] += a2.CMP_ * WV_.y; acc[2][2] += a2.CMP_ * WV_.z; acc[2][3] += a2.CMP_ * WV_.w; \
    acc[3][0] += a3.CMP_ * WV_.x; acc[3][1] += a3.CMP_ * WV_.y; acc[3][2] += a3.CMP_ * WV_.z; acc[3][3] += a3.CMP_ * WV_.w;

template<int KVCOUNT, int SSTRIDE>
__device__ __forceinline__ void gemm16(const float* __restrict__ src,
                                       const float* __restrict__ wcol,
                                       float acc[4][4])
{
    #pragma unroll 2
    for (int kv = 0; kv < KVCOUNT; kv++) {
        float4 a0 = *(const float4*)(src + 0 * SSTRIDE + kv * 4);
        float4 a1 = *(const float4*)(src + 1 * SSTRIDE + kv * 4);
        float4 a2 = *(const float4*)(src + 2 * SSTRIDE + kv * 4);
        float4 a3 = *(const float4*)(src + 3 * SSTRIDE + kv * 4);
        float4 w0 = *(const float4*)(wcol + (kv * 4 + 0) * 64);
        float4 w1 = *(const float4*)(wcol + (kv * 4 + 1) * 64);
        float4 w2 = *(const float4*)(wcol + (kv * 4 + 2) * 64);
        float4 w3 = *(const float4*)(wcol + (kv * 4 + 3) * 64);
        RANK1(x, w0)
        RANK1(y, w1)
        RANK1(z, w2)
        RANK1(w, w3)
    }
}

// ---- fused prologue ----
// blockIdx.x < 80 : hjproj for 8 j-rows (x*8 .. x*8+7), batch blockIdx.y
// blockIdx.x == 80 && blockIdx.y == 0 : W2x = Wm2 @ Wx1 ; b2x
__global__ void __launch_bounds__(256)
prologue_kernel(const float* __restrict__ h, const float* __restrict__ ph,
                const float* __restrict__ Wm1,
                const float* __restrict__ Wm2, const float* __restrict__ Wx1,
                const float* __restrict__ bm2, const float* __restrict__ bx1)
{
    __shared__ float sw[64 * 64];
    __shared__ float sh[8 * 64];
    const int tid = threadIdx.x;

    if (blockIdx.x < 80) {
        const int j0 = blockIdx.x * 8;
        const int b = blockIdx.y;
        {
            const float4* g4 = (const float4*)(Wm1 + 64 * 64);
            float4* s4 = (float4*)sw;
            #pragma unroll
            for (int u = 0; u < 4; u++) s4[tid + u * 256] = g4[tid + u * 256];
        }
        if (tid < 8 * 16) {
            int row = tid >> 4, c = tid & 15;
            int j = j0 + row;
            const float4* hrow = (j < Nn) ? (const float4*)&h[(b * Nn + j) * 64]
                                          : (const float4*)&ph[(b * Pp + (j - Nn)) * 64];
            *(float4*)&sh[row * 64 + c * 4] = hrow[c];
        }
        __syncthreads();

        int row = tid >> 5;      // 0..7
        int c = tid & 31;        // cols c and c+32
        float acc0 = 0.0f, acc1 = 0.0f;
        #pragma unroll 8
        for (int k = 0; k < 64; k++) {
            float a = sh[row * 64 + k];
            acc0 += a * sw[k * 64 + c];
            acc1 += a * sw[k * 64 + c + 32];
        }
        float* op = &g_hjproj[((size_t)(b * NJt) + j0 + row) * 64];
        op[c] = acc0;
        op[c + 32] = acc1;
    } else if (blockIdx.y == 0) {
        __shared__ float sA[64 * 64];
        {
            const float4* g4 = (const float4*)Wx1;
            float4* s4 = (float4*)sw;
            #pragma unroll
            for (int u = 0; u < 4; u++) s4[tid + u * 256] = g4[tid + u * 256];
            g4 = (const float4*)Wm2; s4 = (float4*)sA;
            #pragma unroll
            for (int u = 0; u < 4; u++) s4[tid + u * 256] = g4[tid + u * 256];
        }
        __syncthreads();
        int row = tid >> 2;
        int cq = tid & 3;
        float acc[16] = {};
        #pragma unroll 4
        for (int k = 0; k < 64; k++) {
            float a = sA[row * 64 + k];
            const float* wr = &sw[k * 64 + cq * 16];
            #pragma unroll
            for (int c = 0; c < 16; c++) acc[c] += a * wr[c];
        }
        float4* op = (float4*)&g_W2x[row * 64 + cq * 16];
        op[0] = make_float4(acc[0], acc[1], acc[2], acc[3]);
        op[1] = make_float4(acc[4], acc[5], acc[6], acc[7]);
        op[2] = make_float4(acc[8], acc[9], acc[10], acc[11]);
        op[3] = make_float4(acc[12], acc[13], acc[14], acc[15]);
        if (tid < 64) {
            float bv = bx1[tid];
            #pragma unroll 4
            for (int k = 0; k < 64; k++) bv += bm2[k] * sw[k * 64 + tid];
            g_b2x[tid] = bv;
        }
    }
}

// ---- main: one CTA per (i, b, tile) ; 2 CTAs per SM ----
__global__ void __launch_bounds__(NT, 2)
egnn_kernel(const float* __restrict__ q, const float* __restrict__ x,
            const float* __restrict__ h, const float* __restrict__ e,
            const int* __restrict__ node_mask,
            const float* __restrict__ pq, const float* __restrict__ px,
            const float* __restrict__ pe, const float* __restrict__ ph,
            const int* __restrict__ pmask,
            const float* __restrict__ Wm1, const float* __restrict__ bm1,
            const float* __restrict__ Wx2, const float* __restrict__ bx2)
{
    extern __shared__ float smem_raw[];
    Smem* s = (Smem*)smem_raw;
    const int i = blockIdx.x;
    const int b = blockIdx.y;
    const int tile = blockIdx.z;
    const int j0 = tile * TJ;
    const int tid = threadIdx.x;

    // ---- stage weights & node-i data ----
    {
        const float4* g4 = (const float4*)(Wm1 + 128 * 64);
        float4* s4 = (float4*)s->Wm1;
        for (int idx = tid; idx < 41 * 16; idx += NT) s4[idx] = g4[idx];
        for (int idx = tid; idx < 3 * 16; idx += NT)
            s4[41 * 16 + idx] = make_float4(0.f, 0.f, 0.f, 0.f);
        g4 = (const float4*)g_W2x; s4 = (float4*)s->W2x;
        for (int idx = tid; idx < 1024; idx += NT) s4[idx] = g4[idx];
        g4 = (const float4*)Wx2; s4 = (float4*)s->Wx2;
        for (int idx = tid; idx < 48; idx += NT) s4[idx] = g4[idx];
    }
    if (tid < 64) {
        s->b2x[tid] = g_b2x[tid];
        s->hi[tid] = h[(b * Nn + i) * 64 + tid];
    }
    if (tid < 3) s->bx2[tid] = bx2[tid];
    if (tid < 4) s->qi[tid] = q[(b * Nn + i) * 4 + tid];
    if (tid < 3) s->xi[tid] = x[(b * Nn + i) * 3 + tid];
    __syncthreads();

    // hoisted bias: bm1h = bm1 + hi @ Wm1[0:64]
    if (tid < 64) {
        float acc = bm1[tid];
        #pragma unroll 4
        for (int k = 0; k < 64; k++) acc += s->hi[k] * Wm1[k * 64 + tid];
        s->bm1h[tid] = acc;
    }

    const float qiw = s->qi[0], qix = s->qi[1], qiy = s->qi[2], qiz = s->qi[3];
    const float xi0 = s->xi[0], xi1 = s->xi[1], xi2 = s->xi[2];
    const int mi = node_mask[b * Nn + i];

    const int jb = tid >> 4;      // 0..15 -> block of 4 j rows
    const int cb = tid & 15;      // 0..15 -> block of 4 output cols

    float wx2v[4][3];
    #pragma unroll
    for (int c2 = 0; c2 < 4; c2++)
        #pragma unroll
        for (int cc = 0; cc < 3; cc++)
            wx2v[c2][cc] = s->Wx2[(cb * 4 + c2) * 3 + cc];
    const float bx20 = s->bx2[0], bx21 = s->bx2[1], bx22 = s->bx2[2];

    const float* hjp_base = &g_hjproj[(size_t)b * NJt * 64 + cb * 4];

    // ---------- Phase A: build feature tile ----------
    for (int idx = tid; idx < TJ * 8; idx += NT) {
        int row = idx >> 3, c = idx & 7;
        int j = j0 + row;
        const float4* erow = (j < Nn)
            ? (const float4*)&e[((size_t)(b * Nn + i) * Nn + j) * Ee]
            : (const float4*)&pe[((size_t)(b * Nn + i) * Pp + (j - Nn)) * Ee];
        *(float4*)&s->feat[row * FfB + c * 4] = erow[c];
    }
    if (tid < TJ) {
        int j = j0 + tid;
        float qjw, qjx, qjy, qjz, xj0, xj1, xj2;
        int mj;
        if (j < Nn) {
            const float* qp = &q[(b * Nn + j) * 4];
            qjw = qp[0]; qjx = qp[1]; qjy = qp[2]; qjz = qp[3];
            const float* xp = &x[(b * Nn + j) * 3];
            xj0 = xp[0]; xj1 = xp[1]; xj2 = xp[2];
            mj = (node_mask[b * Nn + j] && (j != i)) ? 1 : 0;
        } else {
            int jp = j - Nn;
            const float* qp = &pq[(b * Pp + jp) * 4];
            qjw = qp[0]; qjx = qp[1]; qjy = qp[2]; qjz = qp[3];
            const float* xp = &px[(b * Pp + jp) * 3];
            xj0 = xp[0]; xj1 = xp[1]; xj2 = xp[2];
            mj = pmask[b * Pp + jp] ? 1 : 0;
        }
        s->maskj[tid] = (mi && mj) ? 1.0f : 0.0f;

        float d0 = xi0 - xj0, d1 = xi1 - xj1, dz = xi2 - xj2;
        float dd = d0 * d0 + d1 * d1 + dz * dz;
        float qd = fabsf(qiw * qjw + qix * qjx + qiy * qjy + qiz * qjz);
        float vx = -qjx, vy = -qjy, vz = -qjz;
        float tx = 2.0f * (vy * dz - vz * d1);
        float ty = 2.0f * (vz * d0 - vx * dz);
        float tz = 2.0f * (vx * d1 - vy * d0);
        float lx0 = d0 + qjw * tx + (vy * tz - vz * ty);
        float lx1 = d1 + qjw * ty + (vz * tx - vx * tz);
        float lx2 = dz + qjw * tz + (vx * ty - vy * tx);
        float lq0 = qjw * qiw - vx * qix - vy * qiy - vz * qiz;
        float lq1 = qjw * qix + vx * qiw + vy * qiz - vz * qiy;
        float lq2 = qjw * qiy - vx * qiz + vy * qiw + vz * qix;
        float lq3 = qjw * qiz + vx * qiy - vy * qix + vz * qiw;
        float* fr = &s->feat[tid * FfB + 32];
        fr[0] = lx0; fr[1] = lx1; fr[2] = lx2;
        fr[3] = lq0; fr[4] = lq1; fr[5] = lq2; fr[6] = lq3;
        fr[7] = dd; fr[8] = qd;
        fr[9] = 0.0f; fr[10] = 0.0f; fr[11] = 0.0f;
        float qn = fmaxf(sqrtf(qjw * qjw + qjx * qjx + qjy * qjy + qjz * qjz), 1e-12f);
        float inv = 1.0f / qn;
        s->rotq[tid * 4 + 0] = qjw * inv;
        s->rotq[tid * 4 + 1] = qjx * inv;
        s->rotq[tid * 4 + 2] = qjy * inv;
        s->rotq[tid * 4 + 3] = qjz * inv;
    }
    __syncthreads();

    float4 hs = make_float4(0.f, 0.f, 0.f, 0.f);
    float xacc0 = 0.0f, xacc1 = 0.0f, xacc2 = 0.0f;

    // ---------- Phase B: hid = relu(featB @ Wm1[128:] + bm1h + hjproj[j]) ----------
    {
        const float* hp = hjp_base + (size_t)(j0 + jb * 4) * 64;
        float4 hp0 = *(const float4*)(hp + 0 * 64);
        float4 hp1 = *(const float4*)(hp + 1 * 64);
        float4 hp2 = *(const float4*)(hp + 2 * 64);
        float4 hp3 = *(const float4*)(hp + 3 * 64);

        float acc[4][4] = {};
        gemm16<FfB / 4, FfB>(&s->feat[(jb * 4) * FfB], &s->Wm1[cb * 4], acc);
        float4 bb = *(const float4*)&s->bm1h[cb * 4];
        float* hr = &s->hid[(jb * 4) * HS + cb * 4];
        float4 hpv[4] = {hp0, hp1, hp2, hp3};
        #pragma unroll
        for (int r = 0; r < 4; r++) {
            float mk = s->maskj[jb * 4 + r];
            float4 o;
            o.x = fmaxf(acc[r][0] + bb.x + hpv[r].x, 0.0f);
            o.y = fmaxf(acc[r][1] + bb.y + hpv[r].y, 0.0f);
            o.z = fmaxf(acc[r][2] + bb.z + hpv[r].z, 0.0f);
            o.w = fmaxf(acc[r][3] + bb.w + hpv[r].w, 0.0f);
            *(float4*)(hr + r * HS) = o;
            hs.x += mk * o.x; hs.y += mk * o.y;
            hs.z += mk * o.z; hs.w += mk * o.w;
        }
    }
    __syncwarp();

    // ---------- Phase D: hid2 = relu(hid @ W2x + b2x) ----------
    float d2[4][4];
    {
        float acc[4][4] = {};
        gemm16<16, HS>(&s->hid[(jb * 4) * HS], &s->W2x[cb * 4], acc);
        float4 bb = *(const float4*)&s->b2x[cb * 4];
        #pragma unroll
        for (int r = 0; r < 4; r++) {
            d2[r][0] = fmaxf(acc[r][0] + bb.x, 0.0f);
            d2[r][1] = fmaxf(acc[r][1] + bb.y, 0.0f);
            d2[r][2] = fmaxf(acc[r][2] + bb.z, 0.0f);
            d2[r][3] = fmaxf(acc[r][3] + bb.w, 0.0f);
        }
    }

    // ---------- Phase E: dx -> 16-lane bfly reduce -> rotate ----------
    {
        float p[4][3];
        #pragma unroll
        for (int r = 0; r < 4; r++) {
            #pragma unroll
            for (int cc = 0; cc < 3; cc++) {
                p[r][cc] = d2[r][0] * wx2v[0][cc] + d2[r][1] * wx2v[1][cc]
                         + d2[r][2] * wx2v[2][cc] + d2[r][3] * wx2v[3][cc];
            }
        }
        #pragma unroll
        for (int mskp = 1; mskp < 16; mskp <<= 1) {
            #pragma unroll
            for (int r = 0; r < 4; r++) {
                #pragma unroll
                for (int cc = 0; cc < 3; cc++)
                    p[r][cc] += __shfl_xor_sync(0xffffffffu, p[r][cc], mskp);
            }
        }
        if (cb < 4) {
            float a0, a1, a2;
            if      (cb == 0) { a0 = p[0][0]; a1 = p[0][1]; a2 = p[0][2]; }
            else if (cb == 1) { a0 = p[1][0]; a1 = p[1][1]; a2 = p[1][2]; }
            else if (cb == 2) { a0 = p[2][0]; a1 = p[2][1]; a2 = p[2][2]; }
            else              { a0 = p[3][0]; a1 = p[3][1]; a2 = p[3][2]; }
            int row = jb * 4 + cb;
            float mk = s->maskj[row];
            a0 = (a0 + bx20) * mk;
            a1 = (a1 + bx21) * mk;
            a2 = (a2 + bx22) * mk;
            float w  = s->rotq[row * 4 + 0];
            float vx = s->rotq[row * 4 + 1];
            float vy = s->rotq[row * 4 + 2];
            float vz = s->rotq[row * 4 + 3];
            float tx = 2.0f * (vy * a2 - vz * a1);
            float ty = 2.0f * (vz * a0 - vx * a2);
            float tz = 2.0f * (vx * a1 - vy * a0);
            xacc0 = a0 + w * tx + (vy * tz - vz * ty);
            xacc1 = a1 + w * ty + (vz * tx - vx * tz);
            xacc2 = a2 + w * tz + (vx * ty - vy * tx);
        }
    }

    // ---- reduce partials, write to global scratch ----
    __syncthreads();
    {
        float* mp = &s->hs_part[jb * 64 + cb * 4];
        mp[0] = hs.x; mp[1] = hs.y; mp[2] = hs.z; mp[3] = hs.w;
    }
    if (cb < 4) {
        int row = jb * 4 + cb;
        s->xpart[row * 3 + 0] = xacc0;
        s->xpart[row * 3 + 1] = xacc1;
        s->xpart[row * 3 + 2] = xacc2;
    }
    __syncthreads();
    const size_t slot = (size_t)((b * Nn + i) * NTILE + tile);
    if (tid < 64) {
        float acc = 0.0f;
        #pragma unroll 4
        for (int g = 0; g < 16; g++) acc += s->hs_part[g * 64 + tid];
        g_hs_part[slot * 64 + tid] = acc;
    }
    if (tid >= 64 && tid < 67) {
        int c = tid - 64;
        float sum = 0.0f;
        #pragma unroll 4
        for (int j = 0; j < TJ; j++) sum += s->xpart[j * 3 + c];
        g_x_part[slot * 4 + c] = sum;
    }
}

// ---- finalize: one block per node ----
__global__ void __launch_bounds__(256)
finalize_kernel(const float* __restrict__ q, const float* __restrict__ x,
                const float* __restrict__ h,
                const int* __restrict__ node_mask, const int* __restrict__ pmask,
                const float* __restrict__ Wm2, const float* __restrict__ bm2,
                const float* __restrict__ Wf1, const float* __restrict__ bf1,
                const float* __restrict__ Wf2, const float* __restrict__ bf2,
                const float* __restrict__ Wq1, const float* __restrict__ bq1,
                const float* __restrict__ Wq2, const float* __restrict__ bq2,
                const float* __restrict__ Wt1, const float* __restrict__ bt1,
                const float* __restrict__ Wt2, const float* __restrict__ bt2,
                float* __restrict__ out)
{
    __shared__ float msum_h[64];
    __shared__ float msum[64];
    __shared__ float hi[64];
    __shared__ float hidf[64];
    __shared__ float hidt[64];
    __shared__ float hidq[64];
    __shared__ float traw[16];
    __shared__ float dqraw[4];
    __shared__ float xacc[4];
    __shared__ float s_nn;

    const int i = blockIdx.x;
    const int b = blockIdx.y;
    const int tid = threadIdx.x;
    const int node = b * Nn + i;
    const size_t base = (size_t)node * NTILE;

    if (tid == 0) s_nn = -1.0f;
    if (tid < 64) {
        float acc = 0.0f;
        #pragma unroll
        for (int t = 0; t < NTILE; t++) acc += g_hs_part[(base + t) * 64 + tid];
        msum_h[tid] = acc;
        hi[tid] = h[node * 64 + tid];
    }
    if (tid >= 64 && tid < 67) {
        int c = tid - 64;
        float acc = 0.0f;
        #pragma unroll
        for (int t = 0; t < NTILE; t++) acc += g_x_part[(base + t) * 4 + c];
        xacc[c] = acc;
    }
    __syncthreads();

    // n_neigh
    {
        float cnt = 0.0f;
        for (int jj = tid; jj < Nn; jj += 256) cnt += node_mask[b * Nn + jj] ? 1.0f : 0.0f;
        for (int jj = tid; jj < Pp; jj += 256) cnt += pmask[b * Pp + jj] ? 1.0f : 0.0f;
        #pragma unroll
        for (int off = 16; off; off >>= 1) cnt += __shfl_down_sync(0xffffffff, cnt, off);
        if ((tid & 31) == 0) atomicAdd(&s_nn, cnt);
    }
    const int mi = node_mask[node];
    __syncthreads();

    // msum = hidsum @ Wm2 + (mi ? nn : 0) * bm2
    if (tid < 64) {
        float acc = (mi ? s_nn : 0.0f) * bm2[tid];
        #pragma unroll 4
        for (int k = 0; k < 64; k++) acc += msum_h[k] * Wm2[k * 64 + tid];
        msum[tid] = acc;
    }
    __syncthreads();

    const int grp = tid >> 6, lt = tid & 63;
    if (grp == 0) {
        float acc = bf1[lt];
        #pragma unroll 4
        for (int k = 0; k < 64; k++) acc += hi[k] * Wf1[k * 64 + lt];
        #pragma unroll 4
        for (int k = 0; k < 64; k++) acc += msum[k] * Wf1[(64 + k) * 64 + lt];
        hidf[lt] = fmaxf(acc, 0.0f);
    } else if (grp == 1) {
        float acc = bt1[lt];
        #pragma unroll 4
        for (int k = 0; k < 64; k++) acc += msum[k] * Wt1[k * 64 + lt];
        hidt[lt] = fmaxf(acc, 0.0f);
    } else if (grp == 2) {
        float acc = bq1[lt];
        #pragma unroll 4
        for (int k = 0; k < 64; k++) acc += msum[k] * Wq1[k * 64 + lt];
        hidq[lt] = fmaxf(acc, 0.0f);
    }
    __syncthreads();

    float* out_q = out;
    float* out_x = out + Bb * Nn * 4;
    float* out_t = out + Bb * Nn * 7;
    float* out_o = out + Bb * Nn * 21;

    if (grp == 0) {
        float acc = bf2[lt];
        #pragma unroll 4
        for (int u = 0; u < 64; u++) acc += hidf[u] * Wf2[u * 64 + lt];
        out_o[node * 64 + lt] = acc;
    } else if (grp == 1 && lt < 14) {
        float acc = bt2[lt];
        #pragma unroll 4
        for (int u = 0; u < 64; u++) acc += hidt[u] * Wt2[u * 14 + lt];
        traw[lt] = acc;
    } else if (grp == 2 && lt < 4) {
        float acc = bq2[lt];
        #pragma unroll 4
        for (int u = 0; u < 64; u++) acc += hidq[u] * Wq2[u * 4 + lt];
        dqraw[lt] = acc;
    }
    __syncthreads();

    if (tid == 0) {
        float qiw = q[node * 4 + 0], qix = q[node * 4 + 1];
        float qiy = q[node * 4 + 2], qiz = q[node * 4 + 3];
        float d0 = dqraw[0], d1 = dqraw[1], d2v = dqraw[2], d3 = dqraw[3];
        if (!mi) { d0 = 1.0f; d1 = 0.0f; d2v = 0.0f; d3 = 0.0f; }
        float nrm = fmaxf(sqrtf(d0 * d0 + d1 * d1 + d2v * d2v + d3 * d3), 1e-12f);
        float inv = 1.0f / nrm;
        d0 *= inv; d1 *= inv; d2v *= inv; d3 *= inv;
        float u0 = qiw * d0 - qix * d1 - qiy * d2v - qiz * d3;
        float u1 = qiw * d1 + qix * d0 + qiy * d3 - qiz * d2v;
        float u2 = qiw * d2v - qix * d3 + qiy * d0 + qiz * d1;
        float u3 = qiw * d3 + qix * d2v - qiy * d1 + qiz * d0;
        if (!mi) { u0 = 1.0f; u1 = 0.0f; u2 = 0.0f; u3 = 0.0f; }
        nrm = fmaxf(sqrtf(u0 * u0 + u1 * u1 + u2 * u2 + u3 * u3), 1e-12f);
        inv = 1.0f / nrm;
        out_q[node * 4 + 0] = u0 * inv;
        out_q[node * 4 + 1] = u1 * inv;
        out_q[node * 4 + 2] = u2 * inv;
        out_q[node * 4 + 3] = u3 * inv;
    }
    if (tid >= 4 && tid < 7) {
        int c = tid - 4;
        out_x[node * 3 + c] = x[node * 3 + c] + xacc[c] / s_nn;
    }
    if (tid >= 32 && tid < 39) {
        int p = tid - 32;
        float a = traw[p * 2 + 0];
        float c = traw[p * 2 + 1];
        float nrm = fmaxf(sqrtf(a * a + c * c), 1e-12f);
        out_t[node * 14 + p * 2 + 0] = a / nrm;
        out_t[node * 14 + p * 2 + 1] = c / nrm;
    }
}

extern "C" void kernel_launch(void* const* d_in, const int* in_sizes, int n_in,
                              void* d_out, int out_size)
{
    const float* q  = (const float*)d_in[0];
    const float* x  = (const float*)d_in[1];
    // d_in[2] = torsions (values unused)
    const float* h  = (const float*)d_in[3];
    const float* e  = (const float*)d_in[4];
    const int* node_mask = (const int*)d_in[5];
    const float* pq = (const float*)d_in[6];
    const float* px = (const float*)d_in[7];
    const float* pe = (const float*)d_in[8];
    const float* ph = (const float*)d_in[9];
    const int* pmask = (const int*)d_in[10];
    const float* Wm1 = (const float*)d_in[11];
    const float* bm1 = (const float*)d_in[12];
    const float* Wm2 = (const float*)d_in[13];
    const float* bm2 = (const float*)d_in[14];
    const float* Wf1 = (const float*)d_in[15];
    const float* bf1 = (const float*)d_in[16];
    const float* Wf2 = (const float*)d_in[17];
    const float* bf2 = (const float*)d_in[18];
    const float* Wx1 = (const float*)d_in[19];
    const float* bx1 = (const float*)d_in[20];
    const float* Wx2 = (const float*)d_in[21];
    const float* bx2 = (const float*)d_in[22];
    const float* Wq1 = (const float*)d_in[23];
    const float* bq1 = (const float*)d_in[24];
    const float* Wq2 = (const float*)d_in[25];
    const float* bq2 = (const float*)d_in[26];
    const float* Wt1 = (const float*)d_in[27];
    const float* bt1 = (const float*)d_in[28];
    const float* Wt2 = (const float*)d_in[29];
    const float* bt2 = (const float*)d_in[30];

    dim3 pgrid(81, Bb);
    prologue_kernel<<<pgrid, 256>>>(h, ph, Wm1, Wm2, Wx1, bm2, bx1);

    const size_t smem = sizeof(Smem);
    cudaFuncSetAttribute(egnn_kernel, cudaFuncAttributeMaxDynamicSharedMemorySize,
                         (int)smem);
    dim3 grid(Nn, Bb, NTILE);
    egnn_kernel<<<grid, NT, smem>>>(q, x, h, e, node_mask, pq, px, pe, ph, pmask,
                                    Wm1, bm1, Wx2, bx2);

    dim3 fgrid(Nn, Bb);
    finalize_kernel<<<fgrid, 256>>>(q, x, h, node_mask, pmask,
                                    Wm2, bm2, Wf1, bf1, Wf2, bf2,
                                    Wq1, bq1, Wq2, bq2, Wt1, bt1, Wt2, bt2,
                                    (float*)d_out);
}